// round 1
// baseline (speedup 1.0000x reference)
#include <cuda_runtime.h>
#include <math.h>

#define N_NODES 50000
#define N_EDGES 800000
#define HEADS   4
#define F       32      // per-head features (HID/HEADS = OUT_DIM = 32)
#define DIM     128     // IN_DIM = HID = HEADS*F

// ---------------- device scratch (no allocation allowed) ----------------
__device__ float g_ft  [N_NODES * DIM];   // ft = x @ W for current conv
__device__ float g_h   [N_NODES * DIM];   // layer-0 output (relu'd), input to layer 1
__device__ float g_el  [N_NODES * HEADS];
__device__ float g_er  [N_NODES * HEADS];
__device__ float g_out1[N_NODES * DIM];   // layer-1 pre-mean output (N,H,F)
__device__ int   g_rowptr[N_NODES + 1];
__device__ int   g_cnt [N_NODES];
__device__ int   g_eidx[N_EDGES];

// ---------------- CSR build ----------------
__global__ void zero_cnt_kernel() {
    int i = blockIdx.x * blockDim.x + threadIdx.x;
    if (i < N_NODES) g_cnt[i] = 0;
}

__global__ void hist_kernel(const int* __restrict__ dst) {
    int i = blockIdx.x * blockDim.x + threadIdx.x;
    if (i < N_EDGES) atomicAdd(&g_cnt[dst[i]], 1);
}

__global__ void scan_kernel() {
    __shared__ int tmp[1024];
    int tid = threadIdx.x;
    const int chunk = (N_NODES + 1023) / 1024;   // 49
    int begin = tid * chunk;
    int end   = begin + chunk; if (end > N_NODES) end = N_NODES;
    int sum = 0;
    for (int i = begin; i < end && begin < N_NODES; i++) sum += g_cnt[i];
    tmp[tid] = sum;
    __syncthreads();
    // Hillis-Steele inclusive scan
    for (int off = 1; off < 1024; off <<= 1) {
        int v = (tid >= off) ? tmp[tid - off] : 0;
        __syncthreads();
        tmp[tid] += v;
        __syncthreads();
    }
    int run = tmp[tid] - sum;   // exclusive prefix
    for (int i = begin; i < end && begin < N_NODES; i++) {
        g_rowptr[i] = run;
        run += g_cnt[i];
    }
    if (tid == 1023) g_rowptr[N_NODES] = tmp[1023];
}

__global__ void scatter_kernel(const int* __restrict__ dst) {
    int i = blockIdx.x * blockDim.x + threadIdx.x;
    if (i < N_EDGES) {
        int d = dst[i];
        int pos = g_rowptr[d] + atomicAdd(&g_cnt[d], 1);
        g_eidx[pos] = i;
    }
}

// ---------------- GEMM: C[M,128] = A[M,128] @ W[128,128], row-major ----------------
// 64-row tile, full 128-col width. 48 KB static smem. Thread tile 8 rows x 4 cols.
__global__ __launch_bounds__(256) void gemm_kernel(
    const float* __restrict__ A, const float* __restrict__ W, float* __restrict__ C)
{
    __shared__ float Ws[64 * 128];   // 32 KB  [kk][n]
    __shared__ float Xs[64 * 64];    // 16 KB  [r][kk]
    int tid = threadIdx.x;
    int m0  = blockIdx.x * 64;
    int tx  = tid & 31;          // col group: cols tx*4 .. tx*4+3
    int ty  = tid >> 5;          // row base: rows ty, ty+8, ..., ty+56

    float acc[8][4];
#pragma unroll
    for (int i = 0; i < 8; i++)
#pragma unroll
        for (int j = 0; j < 4; j++) acc[i][j] = 0.f;

    for (int kb = 0; kb < 128; kb += 64) {
        // load W chunk rows kb..kb+63
        for (int i = tid; i < 64 * 128; i += 256)
            Ws[i] = W[(kb + (i >> 7)) * 128 + (i & 127)];
        // load X chunk
        for (int i = tid; i < 64 * 64; i += 256) {
            int r = i >> 6, kk = i & 63;
            int m = m0 + r;
            Xs[i] = (m < N_NODES) ? A[m * 128 + kb + kk] : 0.f;
        }
        __syncthreads();
#pragma unroll 4
        for (int kk = 0; kk < 64; kk++) {
            float4 b4 = *reinterpret_cast<const float4*>(&Ws[kk * 128 + tx * 4]);
#pragma unroll
            for (int i = 0; i < 8; i++) {
                float a = Xs[(ty + i * 8) * 64 + kk];
                acc[i][0] = fmaf(a, b4.x, acc[i][0]);
                acc[i][1] = fmaf(a, b4.y, acc[i][1]);
                acc[i][2] = fmaf(a, b4.z, acc[i][2]);
                acc[i][3] = fmaf(a, b4.w, acc[i][3]);
            }
        }
        __syncthreads();
    }
#pragma unroll
    for (int i = 0; i < 8; i++) {
        int m = m0 + ty + i * 8;
        if (m < N_NODES) {
            float4 o = make_float4(acc[i][0], acc[i][1], acc[i][2], acc[i][3]);
            *reinterpret_cast<float4*>(&C[m * 128 + tx * 4]) = o;
        }
    }
}

// ---------------- el/er: per (node,head) dot of ft row with attn vectors ----------------
__global__ __launch_bounds__(256) void elr_kernel(
    const float* __restrict__ ft, const float* __restrict__ al, const float* __restrict__ ar)
{
    int w    = (blockIdx.x * blockDim.x + threadIdx.x) >> 5;
    int lane = threadIdx.x & 31;
    if (w >= N_NODES * HEADS) return;
    int node = w >> 2, head = w & 3;
    float v = ft[node * DIM + head * F + lane];
    float l = v * al[head * F + lane];
    float r = v * ar[head * F + lane];
#pragma unroll
    for (int o = 16; o; o >>= 1) {
        l += __shfl_xor_sync(0xffffffffu, l, o);
        r += __shfl_xor_sync(0xffffffffu, r, o);
    }
    if (lane == 0) { g_el[w] = l; g_er[w] = r; }
}

// ---------------- aggregation: warp per (node,head), online softmax ----------------
// out[node*128 + head*32 + lane] = sum_e softmax(score)*w_e*ft[src,head,lane] + bias (relu opt)
__global__ __launch_bounds__(256) void agg_kernel(
    const float* __restrict__ ft, const int* __restrict__ src,
    const float* __restrict__ ew, const float* __restrict__ bias,
    float* __restrict__ out, int do_relu)
{
    int w    = (blockIdx.x * blockDim.x + threadIdx.x) >> 5;
    int lane = threadIdx.x & 31;
    if (w >= N_NODES * HEADS) return;
    int node = w >> 2, head = w & 3;
    int beg = g_rowptr[node], end = g_rowptr[node + 1];
    float erd = g_er[w];

    float m = -INFINITY, s = 0.f, acc = 0.f;
    for (int i = beg; i < end; i++) {
        int   e   = g_eidx[i];
        int   sn  = src[e];
        float wgt = ew[e];
        float sc  = g_el[sn * HEADS + head] + erd;
        sc = (sc > 0.f) ? sc : 0.2f * sc;                 // leaky relu
        float v = ft[sn * DIM + head * F + lane];
        if (sc <= m) {                                    // uniform branch (scalars warp-uniform)
            float p = __expf(sc - m);
            s   += p;
            acc  = fmaf(p * wgt, v, acc);
        } else {
            float sc2 = __expf(m - sc);                   // m=-inf on first edge -> 0
            s   = fmaf(s, sc2, 1.f);
            acc = fmaf(acc, sc2, wgt * v);
            m   = sc;
        }
    }
    float o = acc / fmaxf(s, 1e-9f) + bias[head * F + lane];
    if (do_relu) o = fmaxf(o, 0.f);
    out[node * DIM + head * F + lane] = o;
}

// ---------------- mean over heads (layer 1 epilogue) ----------------
__global__ __launch_bounds__(256) void mean_kernel(
    const float* __restrict__ in, float* __restrict__ out)
{
    int i = blockIdx.x * blockDim.x + threadIdx.x;
    if (i < N_NODES * F) {
        int n = i >> 5, f = i & 31;
        const float* p = in + n * DIM + f;
        out[i] = 0.25f * (p[0] + p[32] + p[64] + p[96]);
    }
}

// ---------------- host orchestration ----------------
extern "C" void kernel_launch(void* const* d_in, const int* in_sizes, int n_in,
                              void* d_out, int out_size)
{
    const float* x_am     = (const float*)d_in[0];
    const float* x_ph     = (const float*)d_in[1];
    const float* exist    = (const float*)d_in[2];
    const float* am_exist = (const float*)d_in[3];

    // Disambiguate input ordering at runtime:
    // dict order:      [x_am, x_ph, exist, am_exist, src, dst, 16 weight tensors]
    // signature order: [x_am, x_ph, exist, am_exist, 16 weight tensors, src, dst]
    const int *src, *dst;
    int wbase;
    if (in_sizes[4] == N_EDGES) { src = (const int*)d_in[4];  dst = (const int*)d_in[5];  wbase = 6; }
    else                        { src = (const int*)d_in[20]; dst = (const int*)d_in[21]; wbase = 4; }

    // weight groups in order: [0]=layer0-am, [1]=layer0-ph, [2]=layer1-am, [3]=layer1-ph
    const float *Wg[4], *alg[4], *arg[4], *bg[4];
    for (int g = 0; g < 4; g++) {
        Wg[g]  = (const float*)d_in[wbase + g * 4 + 0];
        alg[g] = (const float*)d_in[wbase + g * 4 + 1];
        arg[g] = (const float*)d_in[wbase + g * 4 + 2];
        bg[g]  = (const float*)d_in[wbase + g * 4 + 3];
    }

    float* out = (float*)d_out;

    const int ZB = (N_NODES + 255) / 256;
    const int EB = (N_EDGES + 255) / 256;
    const int GB = (N_NODES + 63) / 64;                 // gemm blocks
    const int WB = (N_NODES * HEADS * 32 + 255) / 256;  // warp-per-(node,head) blocks
    const int MB = (N_NODES * F + 255) / 256;

    // --- CSR build (shared by all 4 convs) ---
    zero_cnt_kernel<<<ZB, 256>>>();
    hist_kernel<<<EB, 256>>>(dst);
    scan_kernel<<<1, 1024>>>();
    zero_cnt_kernel<<<ZB, 256>>>();
    scatter_kernel<<<EB, 256>>>(dst);

    float* g_ft_p;   cudaGetSymbolAddress((void**)&g_ft_p,   g_ft);
    float* g_h_p;    cudaGetSymbolAddress((void**)&g_h_p,    g_h);
    float* g_out1_p; cudaGetSymbolAddress((void**)&g_out1_p, g_out1);

    for (int st = 0; st < 2; st++) {   // 0 = am, 1 = ph
        const float* x  = st ? x_ph : x_am;
        const float* ewt = st ? exist : am_exist;
        int g0 = st;        // layer 0 weight group
        int g1 = 2 + st;    // layer 1 weight group

        // layer 0: ft = x@W0 ; scores ; aggregate + bias + relu -> g_h (N,128 flattened)
        gemm_kernel<<<GB, 256>>>(x, Wg[g0], g_ft_p);
        elr_kernel<<<WB, 256>>>(g_ft_p, alg[g0], arg[g0]);
        agg_kernel<<<WB, 256>>>(g_ft_p, src, ewt, bg[g0], g_h_p, 1);

        // layer 1: ft = h@W1 ; scores ; aggregate + bias -> g_out1 ; mean over heads
        gemm_kernel<<<GB, 256>>>(g_h_p, Wg[g1], g_ft_p);
        elr_kernel<<<WB, 256>>>(g_ft_p, alg[g1], arg[g1]);
        agg_kernel<<<WB, 256>>>(g_ft_p, src, ewt, bg[g1], g_out1_p, 0);
        mean_kernel<<<MB, 256>>>(g_out1_p, out + (size_t)st * N_NODES * F);
    }
}

// round 2
// speedup vs baseline: 1.3847x; 1.3847x over previous
#include <cuda_runtime.h>
#include <math.h>

#define N_NODES 50000
#define N_EDGES 800000
#define HEADS   4
#define F       32      // per-head features
#define DIM     128     // IN_DIM = HID = HEADS*F

// ---------------- device scratch ----------------
__device__ float g_ft  [N_NODES * DIM];     // ft = x @ W for current conv
__device__ float g_h   [N_NODES * DIM];     // layer-0 output (relu'd)
__device__ float g_el  [N_NODES * HEADS];   // [node][head], float4-aligned
__device__ float g_er  [N_NODES * HEADS];
__device__ float g_m   [N_NODES * HEADS];   // per (node,head) max score
__device__ float g_is  [N_NODES * HEADS];   // per (node,head) 1/sum(exp)
__device__ float4 g_sc [N_EDGES];           // per CSR-edge scores (4 heads)
__device__ int   g_rowptr[N_NODES + 1];
__device__ int   g_cnt [N_NODES];
__device__ int   g_src_csr[N_EDGES];
__device__ float g_ewa_csr[N_EDGES];
__device__ float g_ewp_csr[N_EDGES];

// ---------------- CSR build ----------------
__global__ void zero_cnt_kernel() {
    int i = blockIdx.x * blockDim.x + threadIdx.x;
    if (i < N_NODES) g_cnt[i] = 0;
}

__global__ void hist_kernel(const int* __restrict__ dst) {
    int i = blockIdx.x * blockDim.x + threadIdx.x;
    if (i < N_EDGES) atomicAdd(&g_cnt[dst[i]], 1);
}

__global__ void scan_kernel() {
    __shared__ int tmp[1024];
    int tid = threadIdx.x;
    const int chunk = (N_NODES + 1023) / 1024;
    int begin = tid * chunk;
    int end   = begin + chunk; if (end > N_NODES) end = N_NODES;
    int sum = 0;
    for (int i = begin; i < end && begin < N_NODES; i++) sum += g_cnt[i];
    tmp[tid] = sum;
    __syncthreads();
    for (int off = 1; off < 1024; off <<= 1) {
        int v = (tid >= off) ? tmp[tid - off] : 0;
        __syncthreads();
        tmp[tid] += v;
        __syncthreads();
    }
    int run = tmp[tid] - sum;
    for (int i = begin; i < end && begin < N_NODES; i++) {
        g_rowptr[i] = run;
        run += g_cnt[i];
    }
    if (tid == 1023) g_rowptr[N_NODES] = tmp[1023];
}

// scatter edges into CSR order, pre-gathering src + both edge-weight streams
__global__ void scatter_kernel(const int* __restrict__ src, const int* __restrict__ dst,
                               const float* __restrict__ ewa, const float* __restrict__ ewp) {
    int i = blockIdx.x * blockDim.x + threadIdx.x;
    if (i < N_EDGES) {
        int d = dst[i];
        int pos = g_rowptr[d] + atomicAdd(&g_cnt[d], 1);
        g_src_csr[pos] = src[i];
        g_ewa_csr[pos] = ewa[i];
        g_ewp_csr[pos] = ewp[i];
    }
}

// ---------------- GEMM: C[M,128] = A[M,128] @ W[128,128] ----------------
__global__ __launch_bounds__(256) void gemm_kernel(
    const float* __restrict__ A, const float* __restrict__ W, float* __restrict__ C)
{
    __shared__ float Ws[64 * 128];
    __shared__ float Xs[64 * 64];
    int tid = threadIdx.x;
    int m0  = blockIdx.x * 64;
    int tx  = tid & 31;
    int ty  = tid >> 5;

    float acc[8][4];
#pragma unroll
    for (int i = 0; i < 8; i++)
#pragma unroll
        for (int j = 0; j < 4; j++) acc[i][j] = 0.f;

    for (int kb = 0; kb < 128; kb += 64) {
        for (int i = tid; i < 64 * 128; i += 256)
            Ws[i] = W[(kb + (i >> 7)) * 128 + (i & 127)];
        for (int i = tid; i < 64 * 64; i += 256) {
            int r = i >> 6, kk = i & 63;
            int m = m0 + r;
            Xs[i] = (m < N_NODES) ? A[m * 128 + kb + kk] : 0.f;
        }
        __syncthreads();
#pragma unroll 4
        for (int kk = 0; kk < 64; kk++) {
            float4 b4 = *reinterpret_cast<const float4*>(&Ws[kk * 128 + tx * 4]);
#pragma unroll
            for (int i = 0; i < 8; i++) {
                float a = Xs[(ty + i * 8) * 64 + kk];
                acc[i][0] = fmaf(a, b4.x, acc[i][0]);
                acc[i][1] = fmaf(a, b4.y, acc[i][1]);
                acc[i][2] = fmaf(a, b4.z, acc[i][2]);
                acc[i][3] = fmaf(a, b4.w, acc[i][3]);
            }
        }
        __syncthreads();
    }
#pragma unroll
    for (int i = 0; i < 8; i++) {
        int m = m0 + ty + i * 8;
        if (m < N_NODES)
            *reinterpret_cast<float4*>(&C[m * 128 + tx * 4]) =
                make_float4(acc[i][0], acc[i][1], acc[i][2], acc[i][3]);
    }
}

// ---------------- el/er ----------------
__global__ __launch_bounds__(256) void elr_kernel(
    const float* __restrict__ ft, const float* __restrict__ al, const float* __restrict__ ar)
{
    int w    = (blockIdx.x * blockDim.x + threadIdx.x) >> 5;
    int lane = threadIdx.x & 31;
    if (w >= N_NODES * HEADS) return;
    int node = w >> 2, head = w & 3;
    float v = ft[node * DIM + head * F + lane];
    float l = v * al[head * F + lane];
    float r = v * ar[head * F + lane];
#pragma unroll
    for (int o = 16; o; o >>= 1) {
        l += __shfl_xor_sync(0xffffffffu, l, o);
        r += __shfl_xor_sync(0xffffffffu, r, o);
    }
    if (lane == 0) { g_el[w] = l; g_er[w] = r; }
}

__device__ __forceinline__ float lrelu(float x) { return x > 0.f ? x : 0.2f * x; }

// ---------------- score + softmax stats: warp per node ----------------
// Writes per-CSR-edge 4-head scores (float4) and per-(node,head) max / 1/sum.
__global__ __launch_bounds__(256) void score_stats_kernel()
{
    int w    = (blockIdx.x * blockDim.x + threadIdx.x) >> 5;
    int lane = threadIdx.x & 31;
    if (w >= N_NODES) return;
    int node = w;
    int beg = g_rowptr[node], end = g_rowptr[node + 1];
    float4 er4 = *reinterpret_cast<const float4*>(&g_er[node * 4]);

    float m[4] = {-INFINITY, -INFINITY, -INFINITY, -INFINITY};
    float s[4] = {0.f, 0.f, 0.f, 0.f};

    for (int i0 = beg; i0 < end; i0 += 32) {
        int i = i0 + lane;
        if (i < end) {
            int sn = g_src_csr[i];
            float4 el4 = *reinterpret_cast<const float4*>(&g_el[sn * 4]);
            float sc[4];
            sc[0] = lrelu(el4.x + er4.x);
            sc[1] = lrelu(el4.y + er4.y);
            sc[2] = lrelu(el4.z + er4.z);
            sc[3] = lrelu(el4.w + er4.w);
            g_sc[i] = make_float4(sc[0], sc[1], sc[2], sc[3]);
#pragma unroll
            for (int h = 0; h < 4; h++) {
                if (sc[h] > m[h]) {                   // rescale running sum
                    s[h] = s[h] * __expf(m[h] - sc[h]) + 1.f;  // exp(-inf)=0 on first
                    m[h] = sc[h];
                } else {
                    s[h] += __expf(sc[h] - m[h]);
                }
            }
        }
    }
    // cross-lane merge of (m, s) pairs
#pragma unroll
    for (int off = 16; off; off >>= 1) {
#pragma unroll
        for (int h = 0; h < 4; h++) {
            float mo = __shfl_xor_sync(0xffffffffu, m[h], off);
            float so = __shfl_xor_sync(0xffffffffu, s[h], off);
            float nm = fmaxf(m[h], mo);
            float t1 = (s[h] > 0.f) ? s[h] * __expf(m[h] - nm) : 0.f;
            float t2 = (so   > 0.f) ? so   * __expf(mo   - nm) : 0.f;
            m[h] = nm; s[h] = t1 + t2;
        }
    }
    if (lane == 0) {
#pragma unroll
        for (int h = 0; h < 4; h++) {
            g_m [node * 4 + h] = isfinite(m[h]) ? m[h] : 0.f;
            g_is[node * 4 + h] = 1.f / fmaxf(s[h], 1e-9f);
        }
    }
}

// ---------------- aggregation: warp per node, all 4 heads ----------------
// mode 0: out[node][128] = relu(agg + bias)
// mode 1: out[node][32]  = mean_h(agg + bias)
__global__ __launch_bounds__(256) void agg_kernel(
    const float* __restrict__ ft, const float* __restrict__ ewc,
    const float* __restrict__ bias, float* __restrict__ out, int mode)
{
    int w    = (blockIdx.x * blockDim.x + threadIdx.x) >> 5;
    int lane = threadIdx.x & 31;
    if (w >= N_NODES) return;
    int node = w;
    int beg = g_rowptr[node], end = g_rowptr[node + 1];
    int h = lane >> 3;                       // head handled by this lane group
    int f0 = (lane & 7) * 4;                 // feature offset within head

    float mh = g_m [node * 4 + h];
    float is = g_is[node * 4 + h];

    float4 acc = make_float4(0.f, 0.f, 0.f, 0.f);

    int i = beg;
    int sn0 = (i < end) ? g_src_csr[i] : 0;
    for (; i < end; i++) {
        // issue the gather for this edge, prefetch next src
        const float4 v = *reinterpret_cast<const float4*>(&ft[(size_t)sn0 * DIM + lane * 4]);
        int sn1 = (i + 1 < end) ? g_src_csr[i + 1] : 0;
        float4 sc4 = g_sc[i];
        float  ew  = ewc[i];
        float  sc  = (h == 0) ? sc4.x : (h == 1) ? sc4.y : (h == 2) ? sc4.z : sc4.w;
        float  p   = __expf(sc - mh) * is * ew;
        acc.x = fmaf(p, v.x, acc.x);
        acc.y = fmaf(p, v.y, acc.y);
        acc.z = fmaf(p, v.z, acc.z);
        acc.w = fmaf(p, v.w, acc.w);
        sn0 = sn1;
    }

    float4 b4 = *reinterpret_cast<const float4*>(&bias[h * F + f0]);
    acc.x += b4.x; acc.y += b4.y; acc.z += b4.z; acc.w += b4.w;

    if (mode == 0) {
        acc.x = fmaxf(acc.x, 0.f); acc.y = fmaxf(acc.y, 0.f);
        acc.z = fmaxf(acc.z, 0.f); acc.w = fmaxf(acc.w, 0.f);
        *reinterpret_cast<float4*>(&out[(size_t)node * DIM + lane * 4]) = acc;
    } else {
        // mean over heads: lanes l, l^8, l^16, l^24 hold same features, diff heads
#pragma unroll
        for (int off = 8; off <= 16; off <<= 1) {
            acc.x += __shfl_xor_sync(0xffffffffu, acc.x, off);
            acc.y += __shfl_xor_sync(0xffffffffu, acc.y, off);
            acc.z += __shfl_xor_sync(0xffffffffu, acc.z, off);
            acc.w += __shfl_xor_sync(0xffffffffu, acc.w, off);
        }
        if (lane < 8) {
            float4 o = make_float4(0.25f * acc.x, 0.25f * acc.y,
                                   0.25f * acc.z, 0.25f * acc.w);
            *reinterpret_cast<float4*>(&out[(size_t)node * F + f0]) = o;
        }
    }
}

// ---------------- host orchestration ----------------
extern "C" void kernel_launch(void* const* d_in, const int* in_sizes, int n_in,
                              void* d_out, int out_size)
{
    const float* x_am     = (const float*)d_in[0];
    const float* x_ph     = (const float*)d_in[1];
    const float* exist    = (const float*)d_in[2];
    const float* am_exist = (const float*)d_in[3];

    const int *src, *dst;
    int wbase;
    if (in_sizes[4] == N_EDGES) { src = (const int*)d_in[4];  dst = (const int*)d_in[5];  wbase = 6; }
    else                        { src = (const int*)d_in[20]; dst = (const int*)d_in[21]; wbase = 4; }

    const float *Wg[4], *alg[4], *arg[4], *bg[4];
    for (int g = 0; g < 4; g++) {
        Wg[g]  = (const float*)d_in[wbase + g * 4 + 0];
        alg[g] = (const float*)d_in[wbase + g * 4 + 1];
        arg[g] = (const float*)d_in[wbase + g * 4 + 2];
        bg[g]  = (const float*)d_in[wbase + g * 4 + 3];
    }

    float* out = (float*)d_out;

    const int ZB = (N_NODES + 255) / 256;
    const int EB = (N_EDGES + 255) / 256;
    const int GB = (N_NODES + 63) / 64;
    const int WB = (N_NODES * HEADS * 32 + 255) / 256;   // warp-per-(node,head)
    const int NB = (N_NODES * 32 + 255) / 256;           // warp-per-node

    zero_cnt_kernel<<<ZB, 256>>>();
    hist_kernel<<<EB, 256>>>(dst);
    scan_kernel<<<1, 1024>>>();
    zero_cnt_kernel<<<ZB, 256>>>();
    scatter_kernel<<<EB, 256>>>(src, dst, am_exist, exist);

    float* g_ft_p;  cudaGetSymbolAddress((void**)&g_ft_p, g_ft);
    float* g_h_p;   cudaGetSymbolAddress((void**)&g_h_p,  g_h);
    float* ewa_p;   cudaGetSymbolAddress((void**)&ewa_p,  g_ewa_csr);
    float* ewp_p;   cudaGetSymbolAddress((void**)&ewp_p,  g_ewp_csr);

    for (int st = 0; st < 2; st++) {
        const float* x   = st ? x_ph  : x_am;
        const float* ewc = st ? ewp_p : ewa_p;
        int g0 = st, g1 = 2 + st;

        // layer 0
        gemm_kernel<<<GB, 256>>>(x, Wg[g0], g_ft_p);
        elr_kernel<<<WB, 256>>>(g_ft_p, alg[g0], arg[g0]);
        score_stats_kernel<<<NB, 256>>>();
        agg_kernel<<<NB, 256>>>(g_ft_p, ewc, bg[g0], g_h_p, 0);

        // layer 1 (+ fused head-mean)
        gemm_kernel<<<GB, 256>>>(g_h_p, Wg[g1], g_ft_p);
        elr_kernel<<<WB, 256>>>(g_ft_p, alg[g1], arg[g1]);
        score_stats_kernel<<<NB, 256>>>();
        agg_kernel<<<NB, 256>>>(g_ft_p, ewc, bg[g1], out + (size_t)st * N_NODES * F, 1);
    }
}

// round 3
// speedup vs baseline: 1.7975x; 1.2981x over previous
#include <cuda_runtime.h>
#include <math.h>

#define N_NODES 50000
#define N_EDGES 800000
#define HEADS   4
#define F       32
#define DIM     128

// ---------------- device scratch ----------------
__device__ float g_ft  [N_NODES * DIM];
__device__ float g_h   [N_NODES * DIM];
__device__ float g_el  [N_NODES * HEADS];
__device__ float g_er  [N_NODES * HEADS];
__device__ float4 g_sc [N_EDGES];           // pass1: scores; pass2: p = exp(sc-m)/s*ew
__device__ int   g_rowptr[N_NODES + 1];
__device__ int   g_cnt [N_NODES];
__device__ int   g_src_csr[N_EDGES];
__device__ float g_ewa_csr[N_EDGES];
__device__ float g_ewp_csr[N_EDGES];

// ---------------- CSR build ----------------
__global__ void zero_cnt_kernel() {
    int i = blockIdx.x * blockDim.x + threadIdx.x;
    if (i < N_NODES) g_cnt[i] = 0;
}

__global__ void hist_kernel(const int* __restrict__ dst) {
    int i = blockIdx.x * blockDim.x + threadIdx.x;
    if (i < N_EDGES) atomicAdd(&g_cnt[dst[i]], 1);
}

__global__ void scan_kernel() {
    __shared__ int tmp[1024];
    int tid = threadIdx.x;
    const int chunk = (N_NODES + 1023) / 1024;
    int begin = tid * chunk;
    int end   = begin + chunk; if (end > N_NODES) end = N_NODES;
    int sum = 0;
    for (int i = begin; i < end && begin < N_NODES; i++) sum += g_cnt[i];
    tmp[tid] = sum;
    __syncthreads();
    for (int off = 1; off < 1024; off <<= 1) {
        int v = (tid >= off) ? tmp[tid - off] : 0;
        __syncthreads();
        tmp[tid] += v;
        __syncthreads();
    }
    int run = tmp[tid] - sum;
    for (int i = begin; i < end && begin < N_NODES; i++) {
        g_rowptr[i] = run;
        run += g_cnt[i];
    }
    if (tid == 1023) g_rowptr[N_NODES] = tmp[1023];
}

__global__ void scatter_kernel(const int* __restrict__ src, const int* __restrict__ dst,
                               const float* __restrict__ ewa, const float* __restrict__ ewp) {
    int i = blockIdx.x * blockDim.x + threadIdx.x;
    if (i < N_EDGES) {
        int d = dst[i];
        int pos = g_rowptr[d] + atomicAdd(&g_cnt[d], 1);
        g_src_csr[pos] = src[i];
        g_ewa_csr[pos] = ewa[i];
        g_ewp_csr[pos] = ewp[i];
    }
}

// ---------------- GEMM + fused el/er epilogue ----------------
// C[M,128] = A[M,128] @ W[128,128]; el[r,h] = dot(C[r,h*32:+32], al[h]); er likewise.
__global__ __launch_bounds__(256) void gemm_kernel(
    const float* __restrict__ A, const float* __restrict__ W,
    const float* __restrict__ al, const float* __restrict__ ar,
    float* __restrict__ C)
{
    __shared__ float Ws[64 * 128];
    __shared__ float Xs[64 * 64];
    int tid = threadIdx.x;
    int m0  = blockIdx.x * 64;
    int tx  = tid & 31;
    int ty  = tid >> 5;

    float acc[8][4];
#pragma unroll
    for (int i = 0; i < 8; i++)
#pragma unroll
        for (int j = 0; j < 4; j++) acc[i][j] = 0.f;

    for (int kb = 0; kb < 128; kb += 64) {
        for (int i = tid * 4; i < 64 * 128; i += 1024) {
            float4 w4 = *reinterpret_cast<const float4*>(&W[(kb + (i >> 7)) * 128 + (i & 127)]);
            *reinterpret_cast<float4*>(&Ws[i]) = w4;
        }
        for (int i = tid * 4; i < 64 * 64; i += 1024) {
            int r = i >> 6, kk = i & 63;
            int m = m0 + r;
            float4 x4 = (m < N_NODES)
                ? *reinterpret_cast<const float4*>(&A[m * 128 + kb + kk])
                : make_float4(0.f, 0.f, 0.f, 0.f);
            *reinterpret_cast<float4*>(&Xs[i]) = x4;
        }
        __syncthreads();
#pragma unroll 4
        for (int kk = 0; kk < 64; kk++) {
            float4 b4 = *reinterpret_cast<const float4*>(&Ws[kk * 128 + tx * 4]);
#pragma unroll
            for (int i = 0; i < 8; i++) {
                float a = Xs[(ty + i * 8) * 64 + kk];
                acc[i][0] = fmaf(a, b4.x, acc[i][0]);
                acc[i][1] = fmaf(a, b4.y, acc[i][1]);
                acc[i][2] = fmaf(a, b4.z, acc[i][2]);
                acc[i][3] = fmaf(a, b4.w, acc[i][3]);
            }
        }
        __syncthreads();
    }

    float4 al4 = *reinterpret_cast<const float4*>(&al[tx * 4]);
    float4 ar4 = *reinterpret_cast<const float4*>(&ar[tx * 4]);
    int head = tx >> 3;

#pragma unroll
    for (int i = 0; i < 8; i++) {
        int m = m0 + ty + i * 8;
        if (m < N_NODES)
            *reinterpret_cast<float4*>(&C[m * 128 + tx * 4]) =
                make_float4(acc[i][0], acc[i][1], acc[i][2], acc[i][3]);
        // fused el/er: dot over this thread's 4 cols, reduce across 8 lanes of the head
        float l = acc[i][0] * al4.x + acc[i][1] * al4.y + acc[i][2] * al4.z + acc[i][3] * al4.w;
        float r = acc[i][0] * ar4.x + acc[i][1] * ar4.y + acc[i][2] * ar4.z + acc[i][3] * ar4.w;
#pragma unroll
        for (int off = 1; off <= 4; off <<= 1) {
            l += __shfl_xor_sync(0xffffffffu, l, off);
            r += __shfl_xor_sync(0xffffffffu, r, off);
        }
        if ((tx & 7) == 0 && m < N_NODES) {
            g_el[m * 4 + head] = l;
            g_er[m * 4 + head] = r;
        }
    }
}

__device__ __forceinline__ float lrelu(float x) { return x > 0.f ? x : 0.2f * x; }

// ---------------- score + softmax: warp per node, two passes over edges ----------------
// Pass 1: sc = leakyrelu(el[src]+er[dst]) -> g_sc, online (m, s) per head, warp-merged.
// Pass 2: g_sc[i] = exp(sc - m) / s * ew[i]   (final per-edge weight, 4 heads)
__global__ __launch_bounds__(256) void score_kernel(const float* __restrict__ ewc)
{
    int w    = (blockIdx.x * blockDim.x + threadIdx.x) >> 5;
    int lane = threadIdx.x & 31;
    if (w >= N_NODES) return;
    int node = w;
    int beg = g_rowptr[node], end = g_rowptr[node + 1];
    float4 er4 = *reinterpret_cast<const float4*>(&g_er[node * 4]);

    float m[4] = {-INFINITY, -INFINITY, -INFINITY, -INFINITY};
    float s[4] = {0.f, 0.f, 0.f, 0.f};

    for (int i = beg + lane; i < end; i += 32) {
        int sn = g_src_csr[i];
        float4 el4 = *reinterpret_cast<const float4*>(&g_el[sn * 4]);
        float sc[4];
        sc[0] = lrelu(el4.x + er4.x);
        sc[1] = lrelu(el4.y + er4.y);
        sc[2] = lrelu(el4.z + er4.z);
        sc[3] = lrelu(el4.w + er4.w);
        g_sc[i] = make_float4(sc[0], sc[1], sc[2], sc[3]);
#pragma unroll
        for (int h = 0; h < 4; h++) {
            if (sc[h] > m[h]) {
                s[h] = s[h] * __expf(m[h] - sc[h]) + 1.f;
                m[h] = sc[h];
            } else {
                s[h] += __expf(sc[h] - m[h]);
            }
        }
    }
#pragma unroll
    for (int off = 16; off; off >>= 1) {
#pragma unroll
        for (int h = 0; h < 4; h++) {
            float mo = __shfl_xor_sync(0xffffffffu, m[h], off);
            float so = __shfl_xor_sync(0xffffffffu, s[h], off);
            float nm = fmaxf(m[h], mo);
            float t1 = (s[h] > 0.f) ? s[h] * __expf(m[h] - nm) : 0.f;
            float t2 = (so   > 0.f) ? so   * __expf(mo   - nm) : 0.f;
            m[h] = nm; s[h] = t1 + t2;
        }
    }
    float is[4];
#pragma unroll
    for (int h = 0; h < 4; h++) {
        if (!isfinite(m[h])) m[h] = 0.f;
        is[h] = 1.f / fmaxf(s[h], 1e-9f);
    }
    // pass 2: finalize per-edge weights (sequential, L2-hot)
    for (int i = beg + lane; i < end; i += 32) {
        float4 sc = g_sc[i];
        float  ew = ewc[i];
        sc.x = __expf(sc.x - m[0]) * is[0] * ew;
        sc.y = __expf(sc.y - m[1]) * is[1] * ew;
        sc.z = __expf(sc.z - m[2]) * is[2] * ew;
        sc.w = __expf(sc.w - m[3]) * is[3] * ew;
        g_sc[i] = sc;
    }
}

// ---------------- aggregation: warp per node, 4-wide pipelined gathers ----------------
// mode 0: out[node][128] = relu(agg + bias);  mode 1: out[node][32] = mean_h(agg + bias)
__global__ __launch_bounds__(256) void agg_kernel(
    const float* __restrict__ ft, const float* __restrict__ bias,
    float* __restrict__ out, int mode)
{
    __shared__ float sh_p[8][128];     // per warp: 32 edges x 4 heads
    int wib  = threadIdx.x >> 5;       // warp in block
    int w    = (blockIdx.x * blockDim.x + threadIdx.x) >> 5;
    int lane = threadIdx.x & 31;
    if (w >= N_NODES) return;
    int node = w;
    int beg = g_rowptr[node], end = g_rowptr[node + 1];
    int h  = lane >> 3;
    int f0 = (lane & 7) * 4;
    float* pw = sh_p[wib];

    float4 acc = make_float4(0.f, 0.f, 0.f, 0.f);

    for (int i0 = beg; i0 < end; i0 += 32) {
        int n = end - i0; if (n > 32) n = 32;
        int   sn_l = (lane < n) ? g_src_csr[i0 + lane] : 0;
        float4 p4  = (lane < n) ? g_sc[i0 + lane] : make_float4(0.f, 0.f, 0.f, 0.f);
        __syncwarp();
        *reinterpret_cast<float4*>(&pw[lane * 4]) = p4;
        __syncwarp();

        int j = 0;
        for (; j + 4 <= n; j += 4) {
            int s0 = __shfl_sync(0xffffffffu, sn_l, j);
            int s1 = __shfl_sync(0xffffffffu, sn_l, j + 1);
            int s2 = __shfl_sync(0xffffffffu, sn_l, j + 2);
            int s3 = __shfl_sync(0xffffffffu, sn_l, j + 3);
            float4 v0 = *reinterpret_cast<const float4*>(&ft[s0 * DIM + lane * 4]);
            float4 v1 = *reinterpret_cast<const float4*>(&ft[s1 * DIM + lane * 4]);
            float4 v2 = *reinterpret_cast<const float4*>(&ft[s2 * DIM + lane * 4]);
            float4 v3 = *reinterpret_cast<const float4*>(&ft[s3 * DIM + lane * 4]);
            float p0 = pw[(j    ) * 4 + h];
            float p1 = pw[(j + 1) * 4 + h];
            float p2 = pw[(j + 2) * 4 + h];
            float p3 = pw[(j + 3) * 4 + h];
            acc.x = fmaf(p0, v0.x, acc.x); acc.y = fmaf(p0, v0.y, acc.y);
            acc.z = fmaf(p0, v0.z, acc.z); acc.w = fmaf(p0, v0.w, acc.w);
            acc.x = fmaf(p1, v1.x, acc.x); acc.y = fmaf(p1, v1.y, acc.y);
            acc.z = fmaf(p1, v1.z, acc.z); acc.w = fmaf(p1, v1.w, acc.w);
            acc.x = fmaf(p2, v2.x, acc.x); acc.y = fmaf(p2, v2.y, acc.y);
            acc.z = fmaf(p2, v2.z, acc.z); acc.w = fmaf(p2, v2.w, acc.w);
            acc.x = fmaf(p3, v3.x, acc.x); acc.y = fmaf(p3, v3.y, acc.y);
            acc.z = fmaf(p3, v3.z, acc.z); acc.w = fmaf(p3, v3.w, acc.w);
        }
        for (; j < n; j++) {
            int sj = __shfl_sync(0xffffffffu, sn_l, j);
            float4 v = *reinterpret_cast<const float4*>(&ft[sj * DIM + lane * 4]);
            float p = pw[j * 4 + h];
            acc.x = fmaf(p, v.x, acc.x); acc.y = fmaf(p, v.y, acc.y);
            acc.z = fmaf(p, v.z, acc.z); acc.w = fmaf(p, v.w, acc.w);
        }
    }

    float4 b4 = *reinterpret_cast<const float4*>(&bias[h * F + f0]);
    acc.x += b4.x; acc.y += b4.y; acc.z += b4.z; acc.w += b4.w;

    if (mode == 0) {
        acc.x = fmaxf(acc.x, 0.f); acc.y = fmaxf(acc.y, 0.f);
        acc.z = fmaxf(acc.z, 0.f); acc.w = fmaxf(acc.w, 0.f);
        *reinterpret_cast<float4*>(&out[node * DIM + lane * 4]) = acc;
    } else {
#pragma unroll
        for (int off = 8; off <= 16; off <<= 1) {
            acc.x += __shfl_xor_sync(0xffffffffu, acc.x, off);
            acc.y += __shfl_xor_sync(0xffffffffu, acc.y, off);
            acc.z += __shfl_xor_sync(0xffffffffu, acc.z, off);
            acc.w += __shfl_xor_sync(0xffffffffu, acc.w, off);
        }
        if (lane < 8) {
            *reinterpret_cast<float4*>(&out[node * F + f0]) =
                make_float4(0.25f * acc.x, 0.25f * acc.y, 0.25f * acc.z, 0.25f * acc.w);
        }
    }
}

// ---------------- host orchestration ----------------
extern "C" void kernel_launch(void* const* d_in, const int* in_sizes, int n_in,
                              void* d_out, int out_size)
{
    const float* x_am     = (const float*)d_in[0];
    const float* x_ph     = (const float*)d_in[1];
    const float* exist    = (const float*)d_in[2];
    const float* am_exist = (const float*)d_in[3];

    const int *src, *dst;
    int wbase;
    if (in_sizes[4] == N_EDGES) { src = (const int*)d_in[4];  dst = (const int*)d_in[5];  wbase = 6; }
    else                        { src = (const int*)d_in[20]; dst = (const int*)d_in[21]; wbase = 4; }

    const float *Wg[4], *alg[4], *arg[4], *bg[4];
    for (int g = 0; g < 4; g++) {
        Wg[g]  = (const float*)d_in[wbase + g * 4 + 0];
        alg[g] = (const float*)d_in[wbase + g * 4 + 1];
        arg[g] = (const float*)d_in[wbase + g * 4 + 2];
        bg[g]  = (const float*)d_in[wbase + g * 4 + 3];
    }

    float* out = (float*)d_out;

    const int ZB = (N_NODES + 255) / 256;
    const int EB = (N_EDGES + 255) / 256;
    const int GB = (N_NODES + 63) / 64;
    const int NB = (N_NODES * 32 + 255) / 256;   // warp-per-node

    zero_cnt_kernel<<<ZB, 256>>>();
    hist_kernel<<<EB, 256>>>(dst);
    scan_kernel<<<1, 1024>>>();
    zero_cnt_kernel<<<ZB, 256>>>();
    scatter_kernel<<<EB, 256>>>(src, dst, am_exist, exist);

    float* g_ft_p;  cudaGetSymbolAddress((void**)&g_ft_p, g_ft);
    float* g_h_p;   cudaGetSymbolAddress((void**)&g_h_p,  g_h);
    float* ewa_p;   cudaGetSymbolAddress((void**)&ewa_p,  g_ewa_csr);
    float* ewp_p;   cudaGetSymbolAddress((void**)&ewp_p,  g_ewp_csr);

    for (int st = 0; st < 2; st++) {
        const float* x   = st ? x_ph  : x_am;
        const float* ewc = st ? ewp_p : ewa_p;
        int g0 = st, g1 = 2 + st;

        // layer 0
        gemm_kernel<<<GB, 256>>>(x, Wg[g0], alg[g0], arg[g0], g_ft_p);
        score_kernel<<<NB, 256>>>(ewc);
        agg_kernel<<<NB, 256>>>(g_ft_p, bg[g0], g_h_p, 0);

        // layer 1 (+ fused head-mean)
        gemm_kernel<<<GB, 256>>>(g_h_p, Wg[g1], alg[g1], arg[g1], g_ft_p);
        score_kernel<<<NB, 256>>>(ewc);
        agg_kernel<<<NB, 256>>>(g_ft_p, bg[g1], out + (size_t)st * N_NODES * F, 1);
    }
}

// round 4
// speedup vs baseline: 1.8874x; 1.0500x over previous
#include <cuda_runtime.h>
#include <math.h>

#define N_NODES 50000
#define N_EDGES 800000
#define HEADS   4
#define F       32
#define DIM     128

typedef unsigned long long ull;

// ---------------- device scratch ----------------
__device__ float g_ft_a[N_NODES * DIM];
__device__ float g_ft_p[N_NODES * DIM];
__device__ float g_h_a [N_NODES * DIM];
__device__ float g_h_p [N_NODES * DIM];
__device__ float g_el_a[N_NODES * HEADS];
__device__ float g_er_a[N_NODES * HEADS];
__device__ float g_el_p[N_NODES * HEADS];
__device__ float g_er_p[N_NODES * HEADS];
__device__ float4 g_sc_a[N_EDGES];
__device__ float4 g_sc_p[N_EDGES];
__device__ int   g_rowptr[N_NODES + 1];
__device__ int   g_cnt [N_NODES];
__device__ int   g_src_csr[N_EDGES];
__device__ float g_ewa_csr[N_EDGES];
__device__ float g_ewp_csr[N_EDGES];

// ---------------- f32x2 helpers ----------------
__device__ __forceinline__ ull dup2(float v) {
    ull r; asm("mov.b64 %0, {%1, %1};" : "=l"(r) : "f"(v)); return r;
}
__device__ __forceinline__ ull pk2(float a, float b) {
    ull r; asm("mov.b64 %0, {%1, %2};" : "=l"(r) : "f"(a), "f"(b)); return r;
}
__device__ __forceinline__ void ffma2(ull& d, ull a, ull b) {
    asm("fma.rn.f32x2 %0, %1, %2, %3;" : "=l"(d) : "l"(a), "l"(b), "l"(d));
}
__device__ __forceinline__ void unpk2(ull v, float& lo, float& hi) {
    asm("mov.b64 {%0, %1}, %2;" : "=f"(lo), "=f"(hi) : "l"(v));
}

// ---------------- CSR build ----------------
__global__ void zero_cnt_kernel() {
    int i = blockIdx.x * blockDim.x + threadIdx.x;
    if (i < N_NODES) g_cnt[i] = 0;
}

__global__ void hist_kernel(const int* __restrict__ dst) {
    int i = blockIdx.x * blockDim.x + threadIdx.x;
    if (i < N_EDGES) atomicAdd(&g_cnt[dst[i]], 1);
}

__global__ void scan_kernel() {
    __shared__ int tmp[1024];
    int tid = threadIdx.x;
    const int chunk = (N_NODES + 1023) / 1024;
    int begin = tid * chunk;
    int end   = begin + chunk; if (end > N_NODES) end = N_NODES;
    int sum = 0;
    for (int i = begin; i < end && begin < N_NODES; i++) sum += g_cnt[i];
    tmp[tid] = sum;
    __syncthreads();
    for (int off = 1; off < 1024; off <<= 1) {
        int v = (tid >= off) ? tmp[tid - off] : 0;
        __syncthreads();
        tmp[tid] += v;
        __syncthreads();
    }
    int run = tmp[tid] - sum;
    for (int i = begin; i < end && begin < N_NODES; i++) {
        g_rowptr[i] = run;
        run += g_cnt[i];
    }
    if (tid == 1023) g_rowptr[N_NODES] = tmp[1023];
}

__global__ void scatter_kernel(const int* __restrict__ src, const int* __restrict__ dst,
                               const float* __restrict__ ewa, const float* __restrict__ ewp) {
    int i = blockIdx.x * blockDim.x + threadIdx.x;
    if (i < N_EDGES) {
        int d = dst[i];
        int pos = g_rowptr[d] + atomicAdd(&g_cnt[d], 1);
        g_src_csr[pos] = src[i];
        g_ewa_csr[pos] = ewa[i];
        g_ewp_csr[pos] = ewp[i];
    }
}

// ---------------- GEMM (f32x2) + fused el/er; grid.y selects stream ----------------
__global__ __launch_bounds__(256) void gemm_kernel(
    const float* __restrict__ A0, const float* __restrict__ A1,
    const float* __restrict__ W0, const float* __restrict__ W1,
    const float* __restrict__ al0, const float* __restrict__ al1,
    const float* __restrict__ ar0, const float* __restrict__ ar1,
    float* __restrict__ C0, float* __restrict__ C1,
    float* __restrict__ el0, float* __restrict__ el1,
    float* __restrict__ er0, float* __restrict__ er1)
{
    int st = blockIdx.y;
    const float* A  = st ? A1  : A0;
    const float* W  = st ? W1  : W0;
    const float* al = st ? al1 : al0;
    const float* ar = st ? ar1 : ar0;
    float* C  = st ? C1  : C0;
    float* el = st ? el1 : el0;
    float* er = st ? er1 : er0;

    __shared__ __align__(16) float Ws[32 * 128];   // 16 KB [kk][n]
    __shared__ __align__(16) float Xs[32 * 128];   // 16 KB [kk][2r] duplicated {a,a}

    int tid = threadIdx.x;
    int m0  = blockIdx.x * 64;
    int tx  = tid & 31;          // 4 cols: tx*4..tx*4+3
    int ty  = tid >> 5;          // 8 rows: ty*8..ty*8+7

    ull acc[8][2];
#pragma unroll
    for (int i = 0; i < 8; i++) { acc[i][0] = 0ull; acc[i][1] = 0ull; }

    ull* Xp = (ull*)Xs;

    for (int kb = 0; kb < 128; kb += 32) {
        // W rows kb..kb+31
        for (int i = tid * 4; i < 32 * 128; i += 1024)
            *reinterpret_cast<float4*>(&Ws[i]) =
                *reinterpret_cast<const float4*>(&W[(kb + (i >> 7)) * 128 + (i & 127)]);
        // X duplicated: Xp[kk*64 + r] = {A[m0+r][kb+kk], same}
        for (int i = tid; i < 64 * 8; i += 256) {
            int r = i & 63, kk4 = i >> 6;
            int m = m0 + r;
            float4 x4 = (m < N_NODES)
                ? *reinterpret_cast<const float4*>(&A[m * 128 + kb + kk4 * 4])
                : make_float4(0.f, 0.f, 0.f, 0.f);
            Xp[(kk4 * 4 + 0) * 64 + r] = dup2(x4.x);
            Xp[(kk4 * 4 + 1) * 64 + r] = dup2(x4.y);
            Xp[(kk4 * 4 + 2) * 64 + r] = dup2(x4.z);
            Xp[(kk4 * 4 + 3) * 64 + r] = dup2(x4.w);
        }
        __syncthreads();
#pragma unroll 8
        for (int kk = 0; kk < 32; kk++) {
            float4 b4 = *reinterpret_cast<const float4*>(&Ws[kk * 128 + tx * 4]);
            ull b01 = pk2(b4.x, b4.y);
            ull b23 = pk2(b4.z, b4.w);
            const ull* xrow = &Xp[kk * 64 + ty * 8];
#pragma unroll
            for (int p = 0; p < 8; p++) {
                ull aa = xrow[p];
                ffma2(acc[p][0], aa, b01);
                ffma2(acc[p][1], aa, b23);
            }
        }
        __syncthreads();
    }

    float4 al4 = *reinterpret_cast<const float4*>(&al[tx * 4]);
    float4 ar4 = *reinterpret_cast<const float4*>(&ar[tx * 4]);
    int head = tx >> 3;

#pragma unroll
    for (int p = 0; p < 8; p++) {
        float4 o;
        unpk2(acc[p][0], o.x, o.y);
        unpk2(acc[p][1], o.z, o.w);
        int m = m0 + ty * 8 + p;
        if (m < N_NODES)
            *reinterpret_cast<float4*>(&C[m * 128 + tx * 4]) = o;
        float l = o.x * al4.x + o.y * al4.y + o.z * al4.z + o.w * al4.w;
        float r = o.x * ar4.x + o.y * ar4.y + o.z * ar4.z + o.w * ar4.w;
#pragma unroll
        for (int off = 1; off <= 4; off <<= 1) {
            l += __shfl_xor_sync(0xffffffffu, l, off);
            r += __shfl_xor_sync(0xffffffffu, r, off);
        }
        if ((tx & 7) == 0 && m < N_NODES) {
            el[m * 4 + head] = l;
            er[m * 4 + head] = r;
        }
    }
}

__device__ __forceinline__ float lrelu(float x) { return x > 0.f ? x : 0.2f * x; }

// ---------------- score + softmax: warp per node, BOTH streams ----------------
__global__ __launch_bounds__(256) void score_kernel(
    const float* __restrict__ ewa, const float* __restrict__ ewp)
{
    int w    = (blockIdx.x * blockDim.x + threadIdx.x) >> 5;
    int lane = threadIdx.x & 31;
    if (w >= N_NODES) return;
    int node = w;
    int beg = g_rowptr[node], end = g_rowptr[node + 1];
    float4 erA = *reinterpret_cast<const float4*>(&g_er_a[node * 4]);
    float4 erP = *reinterpret_cast<const float4*>(&g_er_p[node * 4]);

    float m[8], s[8];
#pragma unroll
    for (int h = 0; h < 8; h++) { m[h] = -INFINITY; s[h] = 0.f; }

    for (int i = beg + lane; i < end; i += 32) {
        int sn = g_src_csr[i];
        float4 elA = *reinterpret_cast<const float4*>(&g_el_a[sn * 4]);
        float4 elP = *reinterpret_cast<const float4*>(&g_el_p[sn * 4]);
        float sc[8];
        sc[0] = lrelu(elA.x + erA.x); sc[1] = lrelu(elA.y + erA.y);
        sc[2] = lrelu(elA.z + erA.z); sc[3] = lrelu(elA.w + erA.w);
        sc[4] = lrelu(elP.x + erP.x); sc[5] = lrelu(elP.y + erP.y);
        sc[6] = lrelu(elP.z + erP.z); sc[7] = lrelu(elP.w + erP.w);
        g_sc_a[i] = make_float4(sc[0], sc[1], sc[2], sc[3]);
        g_sc_p[i] = make_float4(sc[4], sc[5], sc[6], sc[7]);
#pragma unroll
        for (int h = 0; h < 8; h++) {
            if (sc[h] > m[h]) {
                s[h] = s[h] * __expf(m[h] - sc[h]) + 1.f;
                m[h] = sc[h];
            } else {
                s[h] += __expf(sc[h] - m[h]);
            }
        }
    }
#pragma unroll
    for (int off = 16; off; off >>= 1) {
#pragma unroll
        for (int h = 0; h < 8; h++) {
            float mo = __shfl_xor_sync(0xffffffffu, m[h], off);
            float so = __shfl_xor_sync(0xffffffffu, s[h], off);
            float nm = fmaxf(m[h], mo);
            float t1 = (s[h] > 0.f) ? s[h] * __expf(m[h] - nm) : 0.f;
            float t2 = (so   > 0.f) ? so   * __expf(mo   - nm) : 0.f;
            m[h] = nm; s[h] = t1 + t2;
        }
    }
    float is[8];
#pragma unroll
    for (int h = 0; h < 8; h++) {
        if (!isfinite(m[h])) m[h] = 0.f;
        is[h] = 1.f / fmaxf(s[h], 1e-9f);
    }
    for (int i = beg + lane; i < end; i += 32) {
        float4 sa = g_sc_a[i];
        float4 sp = g_sc_p[i];
        float  wa = ewa[i];
        float  wp = ewp[i];
        sa.x = __expf(sa.x - m[0]) * is[0] * wa;
        sa.y = __expf(sa.y - m[1]) * is[1] * wa;
        sa.z = __expf(sa.z - m[2]) * is[2] * wa;
        sa.w = __expf(sa.w - m[3]) * is[3] * wa;
        sp.x = __expf(sp.x - m[4]) * is[4] * wp;
        sp.y = __expf(sp.y - m[5]) * is[5] * wp;
        sp.z = __expf(sp.z - m[6]) * is[6] * wp;
        sp.w = __expf(sp.w - m[7]) * is[7] * wp;
        g_sc_a[i] = sa;
        g_sc_p[i] = sp;
    }
}

// ---------------- aggregation: warp per node, BOTH streams ----------------
// mode 0: outX[node][128] = relu(agg + biasX)
// mode 1: outX[node][32]  = mean_h(agg + biasX)
__global__ __launch_bounds__(256) void agg_kernel(
    const float* __restrict__ ftA, const float* __restrict__ ftP,
    const float* __restrict__ biasA, const float* __restrict__ biasP,
    float* __restrict__ outA, float* __restrict__ outP, int mode)
{
    __shared__ float sh_pa[8][128];
    __shared__ float sh_pp[8][128];
    int wib  = threadIdx.x >> 5;
    int w    = (blockIdx.x * blockDim.x + threadIdx.x) >> 5;
    int lane = threadIdx.x & 31;
    if (w >= N_NODES) return;
    int node = w;
    int beg = g_rowptr[node], end = g_rowptr[node + 1];
    int h  = lane >> 3;
    int f0 = (lane & 7) * 4;
    float* pwA = sh_pa[wib];
    float* pwP = sh_pp[wib];

    float4 accA = make_float4(0.f, 0.f, 0.f, 0.f);
    float4 accP = make_float4(0.f, 0.f, 0.f, 0.f);

    for (int i0 = beg; i0 < end; i0 += 32) {
        int n = end - i0; if (n > 32) n = 32;
        int    sn_l = (lane < n) ? g_src_csr[i0 + lane] : 0;
        float4 pa   = (lane < n) ? g_sc_a[i0 + lane] : make_float4(0.f, 0.f, 0.f, 0.f);
        float4 pp   = (lane < n) ? g_sc_p[i0 + lane] : make_float4(0.f, 0.f, 0.f, 0.f);
        __syncwarp();
        *reinterpret_cast<float4*>(&pwA[lane * 4]) = pa;
        *reinterpret_cast<float4*>(&pwP[lane * 4]) = pp;
        __syncwarp();

        int j = 0;
        for (; j + 2 <= n; j += 2) {
            int s0 = __shfl_sync(0xffffffffu, sn_l, j);
            int s1 = __shfl_sync(0xffffffffu, sn_l, j + 1);
            float4 va0 = *reinterpret_cast<const float4*>(&ftA[s0 * DIM + lane * 4]);
            float4 vp0 = *reinterpret_cast<const float4*>(&ftP[s0 * DIM + lane * 4]);
            float4 va1 = *reinterpret_cast<const float4*>(&ftA[s1 * DIM + lane * 4]);
            float4 vp1 = *reinterpret_cast<const float4*>(&ftP[s1 * DIM + lane * 4]);
            float pA0 = pwA[j * 4 + h],       pP0 = pwP[j * 4 + h];
            float pA1 = pwA[(j + 1) * 4 + h], pP1 = pwP[(j + 1) * 4 + h];
            accA.x = fmaf(pA0, va0.x, accA.x); accA.y = fmaf(pA0, va0.y, accA.y);
            accA.z = fmaf(pA0, va0.z, accA.z); accA.w = fmaf(pA0, va0.w, accA.w);
            accP.x = fmaf(pP0, vp0.x, accP.x); accP.y = fmaf(pP0, vp0.y, accP.y);
            accP.z = fmaf(pP0, vp0.z, accP.z); accP.w = fmaf(pP0, vp0.w, accP.w);
            accA.x = fmaf(pA1, va1.x, accA.x); accA.y = fmaf(pA1, va1.y, accA.y);
            accA.z = fmaf(pA1, va1.z, accA.z); accA.w = fmaf(pA1, va1.w, accA.w);
            accP.x = fmaf(pP1, vp1.x, accP.x); accP.y = fmaf(pP1, vp1.y, accP.y);
            accP.z = fmaf(pP1, vp1.z, accP.z); accP.w = fmaf(pP1, vp1.w, accP.w);
        }
        if (j < n) {
            int s0 = __shfl_sync(0xffffffffu, sn_l, j);
            float4 va0 = *reinterpret_cast<const float4*>(&ftA[s0 * DIM + lane * 4]);
            float4 vp0 = *reinterpret_cast<const float4*>(&ftP[s0 * DIM + lane * 4]);
            float pA0 = pwA[j * 4 + h], pP0 = pwP[j * 4 + h];
            accA.x = fmaf(pA0, va0.x, accA.x); accA.y = fmaf(pA0, va0.y, accA.y);
            accA.z = fmaf(pA0, va0.z, accA.z); accA.w = fmaf(pA0, va0.w, accA.w);
            accP.x = fmaf(pP0, vp0.x, accP.x); accP.y = fmaf(pP0, vp0.y, accP.y);
            accP.z = fmaf(pP0, vp0.z, accP.z); accP.w = fmaf(pP0, vp0.w, accP.w);
        }
    }

    float4 bA = *reinterpret_cast<const float4*>(&biasA[h * F + f0]);
    float4 bP = *reinterpret_cast<const float4*>(&biasP[h * F + f0]);
    accA.x += bA.x; accA.y += bA.y; accA.z += bA.z; accA.w += bA.w;
    accP.x += bP.x; accP.y += bP.y; accP.z += bP.z; accP.w += bP.w;

    if (mode == 0) {
        accA.x = fmaxf(accA.x, 0.f); accA.y = fmaxf(accA.y, 0.f);
        accA.z = fmaxf(accA.z, 0.f); accA.w = fmaxf(accA.w, 0.f);
        accP.x = fmaxf(accP.x, 0.f); accP.y = fmaxf(accP.y, 0.f);
        accP.z = fmaxf(accP.z, 0.f); accP.w = fmaxf(accP.w, 0.f);
        *reinterpret_cast<float4*>(&outA[node * DIM + lane * 4]) = accA;
        *reinterpret_cast<float4*>(&outP[node * DIM + lane * 4]) = accP;
    } else {
#pragma unroll
        for (int off = 8; off <= 16; off <<= 1) {
            accA.x += __shfl_xor_sync(0xffffffffu, accA.x, off);
            accA.y += __shfl_xor_sync(0xffffffffu, accA.y, off);
            accA.z += __shfl_xor_sync(0xffffffffu, accA.z, off);
            accA.w += __shfl_xor_sync(0xffffffffu, accA.w, off);
            accP.x += __shfl_xor_sync(0xffffffffu, accP.x, off);
            accP.y += __shfl_xor_sync(0xffffffffu, accP.y, off);
            accP.z += __shfl_xor_sync(0xffffffffu, accP.z, off);
            accP.w += __shfl_xor_sync(0xffffffffu, accP.w, off);
        }
        if (lane < 8) {
            *reinterpret_cast<float4*>(&outA[node * F + f0]) =
                make_float4(0.25f * accA.x, 0.25f * accA.y, 0.25f * accA.z, 0.25f * accA.w);
            *reinterpret_cast<float4*>(&outP[node * F + f0]) =
                make_float4(0.25f * accP.x, 0.25f * accP.y, 0.25f * accP.z, 0.25f * accP.w);
        }
    }
}

// ---------------- host orchestration ----------------
extern "C" void kernel_launch(void* const* d_in, const int* in_sizes, int n_in,
                              void* d_out, int out_size)
{
    const float* x_am     = (const float*)d_in[0];
    const float* x_ph     = (const float*)d_in[1];
    const float* exist    = (const float*)d_in[2];
    const float* am_exist = (const float*)d_in[3];

    const int *src, *dst;
    int wbase;
    if (in_sizes[4] == N_EDGES) { src = (const int*)d_in[4];  dst = (const int*)d_in[5];  wbase = 6; }
    else                        { src = (const int*)d_in[20]; dst = (const int*)d_in[21]; wbase = 4; }

    const float *Wg[4], *alg[4], *arg[4], *bg[4];
    for (int g = 0; g < 4; g++) {
        Wg[g]  = (const float*)d_in[wbase + g * 4 + 0];
        alg[g] = (const float*)d_in[wbase + g * 4 + 1];
        arg[g] = (const float*)d_in[wbase + g * 4 + 2];
        bg[g]  = (const float*)d_in[wbase + g * 4 + 3];
    }

    float* out = (float*)d_out;

    const int ZB = (N_NODES + 255) / 256;
    const int EB = (N_EDGES + 255) / 256;
    const int GB = (N_NODES + 63) / 64;
    const int NB = (N_NODES * 32 + 255) / 256;

    zero_cnt_kernel<<<ZB, 256>>>();
    hist_kernel<<<EB, 256>>>(dst);
    scan_kernel<<<1, 1024>>>();
    zero_cnt_kernel<<<ZB, 256>>>();
    scatter_kernel<<<EB, 256>>>(src, dst, am_exist, exist);

    float *ftA, *ftP, *hA, *hP, *elA, *elP, *erA, *erP, *ewa, *ewp;
    cudaGetSymbolAddress((void**)&ftA, g_ft_a);
    cudaGetSymbolAddress((void**)&ftP, g_ft_p);
    cudaGetSymbolAddress((void**)&hA,  g_h_a);
    cudaGetSymbolAddress((void**)&hP,  g_h_p);
    cudaGetSymbolAddress((void**)&elA, g_el_a);
    cudaGetSymbolAddress((void**)&elP, g_el_p);
    cudaGetSymbolAddress((void**)&erA, g_er_a);
    cudaGetSymbolAddress((void**)&erP, g_er_p);
    cudaGetSymbolAddress((void**)&ewa, g_ewa_csr);
    cudaGetSymbolAddress((void**)&ewp, g_ewp_csr);

    dim3 gg(GB, 2);

    // layer 0 (am = stream 0, ph = stream 1)
    gemm_kernel<<<gg, 256>>>(x_am, x_ph, Wg[0], Wg[1], alg[0], alg[1], arg[0], arg[1],
                             ftA, ftP, elA, elP, erA, erP);
    score_kernel<<<NB, 256>>>(ewa, ewp);
    agg_kernel<<<NB, 256>>>(ftA, ftP, bg[0], bg[1], hA, hP, 0);

    // layer 1 (+ fused head-mean)
    gemm_kernel<<<gg, 256>>>(hA, hP, Wg[2], Wg[3], alg[2], alg[3], arg[2], arg[3],
                             ftA, ftP, elA, elP, erA, erP);
    score_kernel<<<NB, 256>>>(ewa, ewp);
    agg_kernel<<<NB, 256>>>(ftA, ftP, bg[2], bg[3], out, out + (size_t)N_NODES * F, 1);
}

// round 5
// speedup vs baseline: 2.0562x; 1.0895x over previous
#include <cuda_runtime.h>
#include <math.h>

#define N_NODES 50000
#define N_EDGES 800000
#define HEADS   4
#define F       32
#define DIM     128

typedef unsigned long long ull;

// ---------------- device scratch ----------------
__device__ float g_ft_a[N_NODES * DIM];
__device__ float g_ft_p[N_NODES * DIM];
__device__ float g_h_a [N_NODES * DIM];
__device__ float g_h_p [N_NODES * DIM];
__device__ float g_el2 [N_NODES * 8];       // [node][streamA 4 heads | streamP 4 heads]
__device__ float g_er2 [N_NODES * 8];
__device__ float g_is2 [N_NODES * 8];       // 1/sum(exp) per (node, stream, head)
__device__ float g_p   [N_EDGES * 8];       // per-edge p = exp(sc)*ew, both streams
__device__ int   g_rowptr[N_NODES + 1];
__device__ int   g_cnt [N_NODES];
__device__ int   g_src_csr[N_EDGES];
__device__ float2 g_ew_csr[N_EDGES];        // {am_exist, exist}

// ---------------- f32x2 helpers ----------------
__device__ __forceinline__ ull dup2(float v) {
    ull r; asm("mov.b64 %0, {%1, %1};" : "=l"(r) : "f"(v)); return r;
}
__device__ __forceinline__ ull pk2(float a, float b) {
    ull r; asm("mov.b64 %0, {%1, %2};" : "=l"(r) : "f"(a), "f"(b)); return r;
}
__device__ __forceinline__ void ffma2(ull& d, ull a, ull b) {
    asm("fma.rn.f32x2 %0, %1, %2, %3;" : "=l"(d) : "l"(a), "l"(b), "l"(d));
}
__device__ __forceinline__ void unpk2(ull v, float& lo, float& hi) {
    asm("mov.b64 {%0, %1}, %2;" : "=f"(lo), "=f"(hi) : "l"(v));
}

// ---------------- CSR build ----------------
__global__ void zero_cnt_kernel() {
    int i = blockIdx.x * blockDim.x + threadIdx.x;
    if (i < N_NODES) g_cnt[i] = 0;
}

__global__ void hist_kernel(const int* __restrict__ dst) {
    int i = blockIdx.x * blockDim.x + threadIdx.x;
    if (i < N_EDGES) atomicAdd(&g_cnt[dst[i]], 1);
}

// scan + reset cnt to 0 for the scatter pass
__global__ void scan_kernel() {
    __shared__ int tmp[1024];
    int tid = threadIdx.x;
    const int chunk = (N_NODES + 1023) / 1024;
    int begin = tid * chunk;
    int end   = begin + chunk; if (end > N_NODES) end = N_NODES;
    int sum = 0;
    for (int i = begin; i < end && begin < N_NODES; i++) sum += g_cnt[i];
    tmp[tid] = sum;
    __syncthreads();
    for (int off = 1; off < 1024; off <<= 1) {
        int v = (tid >= off) ? tmp[tid - off] : 0;
        __syncthreads();
        tmp[tid] += v;
        __syncthreads();
    }
    int run = tmp[tid] - sum;
    for (int i = begin; i < end && begin < N_NODES; i++) {
        g_rowptr[i] = run;
        run += g_cnt[i];
        g_cnt[i] = 0;
    }
    if (tid == 1023) g_rowptr[N_NODES] = tmp[1023];
}

__global__ void scatter_kernel(const int* __restrict__ src, const int* __restrict__ dst,
                               const float* __restrict__ ewa, const float* __restrict__ ewp) {
    int i = blockIdx.x * blockDim.x + threadIdx.x;
    if (i < N_EDGES) {
        int d = dst[i];
        int pos = g_rowptr[d] + atomicAdd(&g_cnt[d], 1);
        g_src_csr[pos] = src[i];
        g_ew_csr[pos]  = make_float2(ewa[i], ewp[i]);
    }
}

// ---------------- GEMM (f32x2) + fused el/er; grid.y selects stream ----------------
__global__ __launch_bounds__(256) void gemm_kernel(
    const float* __restrict__ A0, const float* __restrict__ A1,
    const float* __restrict__ W0, const float* __restrict__ W1,
    const float* __restrict__ al0, const float* __restrict__ al1,
    const float* __restrict__ ar0, const float* __restrict__ ar1,
    float* __restrict__ C0, float* __restrict__ C1)
{
    int st = blockIdx.y;
    const float* A  = st ? A1  : A0;
    const float* W  = st ? W1  : W0;
    const float* al = st ? al1 : al0;
    const float* ar = st ? ar1 : ar0;
    float* C  = st ? C1  : C0;

    __shared__ __align__(16) float Ws[32 * 128];   // 16 KB [kk][n]
    __shared__ __align__(16) float Xs[32 * 128];   // 16 KB [kk][2r] duplicated {a,a}

    int tid = threadIdx.x;
    int m0  = blockIdx.x * 64;
    int tx  = tid & 31;
    int ty  = tid >> 5;

    ull acc[8][2];
#pragma unroll
    for (int i = 0; i < 8; i++) { acc[i][0] = 0ull; acc[i][1] = 0ull; }

    ull* Xp = (ull*)Xs;

    for (int kb = 0; kb < 128; kb += 32) {
        for (int i = tid * 4; i < 32 * 128; i += 1024)
            *reinterpret_cast<float4*>(&Ws[i]) =
                *reinterpret_cast<const float4*>(&W[(kb + (i >> 7)) * 128 + (i & 127)]);
        for (int i = tid; i < 64 * 8; i += 256) {
            int r = i & 63, kk4 = i >> 6;
            int m = m0 + r;
            float4 x4 = (m < N_NODES)
                ? *reinterpret_cast<const float4*>(&A[m * 128 + kb + kk4 * 4])
                : make_float4(0.f, 0.f, 0.f, 0.f);
            Xp[(kk4 * 4 + 0) * 64 + r] = dup2(x4.x);
            Xp[(kk4 * 4 + 1) * 64 + r] = dup2(x4.y);
            Xp[(kk4 * 4 + 2) * 64 + r] = dup2(x4.z);
            Xp[(kk4 * 4 + 3) * 64 + r] = dup2(x4.w);
        }
        __syncthreads();
#pragma unroll 8
        for (int kk = 0; kk < 32; kk++) {
            float4 b4 = *reinterpret_cast<const float4*>(&Ws[kk * 128 + tx * 4]);
            ull b01 = pk2(b4.x, b4.y);
            ull b23 = pk2(b4.z, b4.w);
            const ulonglong2* xr = reinterpret_cast<const ulonglong2*>(&Xp[kk * 64 + ty * 8]);
            ulonglong2 x01 = xr[0], x23 = xr[1], x45 = xr[2], x67 = xr[3];
            ffma2(acc[0][0], x01.x, b01); ffma2(acc[0][1], x01.x, b23);
            ffma2(acc[1][0], x01.y, b01); ffma2(acc[1][1], x01.y, b23);
            ffma2(acc[2][0], x23.x, b01); ffma2(acc[2][1], x23.x, b23);
            ffma2(acc[3][0], x23.y, b01); ffma2(acc[3][1], x23.y, b23);
            ffma2(acc[4][0], x45.x, b01); ffma2(acc[4][1], x45.x, b23);
            ffma2(acc[5][0], x45.y, b01); ffma2(acc[5][1], x45.y, b23);
            ffma2(acc[6][0], x67.x, b01); ffma2(acc[6][1], x67.x, b23);
            ffma2(acc[7][0], x67.y, b01); ffma2(acc[7][1], x67.y, b23);
        }
        __syncthreads();
    }

    float4 al4 = *reinterpret_cast<const float4*>(&al[tx * 4]);
    float4 ar4 = *reinterpret_cast<const float4*>(&ar[tx * 4]);
    int head = tx >> 3;

#pragma unroll
    for (int p = 0; p < 8; p++) {
        float4 o;
        unpk2(acc[p][0], o.x, o.y);
        unpk2(acc[p][1], o.z, o.w);
        int m = m0 + ty * 8 + p;
        if (m < N_NODES)
            *reinterpret_cast<float4*>(&C[m * 128 + tx * 4]) = o;
        float l = o.x * al4.x + o.y * al4.y + o.z * al4.z + o.w * al4.w;
        float r = o.x * ar4.x + o.y * ar4.y + o.z * ar4.z + o.w * ar4.w;
#pragma unroll
        for (int off = 1; off <= 4; off <<= 1) {
            l += __shfl_xor_sync(0xffffffffu, l, off);
            r += __shfl_xor_sync(0xffffffffu, r, off);
        }
        if ((tx & 7) == 0 && m < N_NODES) {
            g_el2[m * 8 + st * 4 + head] = l;
            g_er2[m * 8 + st * 4 + head] = r;
        }
    }
}

__device__ __forceinline__ float lrelu(float x) { return x > 0.f ? x : 0.2f * x; }

// ---------------- score: ONE pass. p = exp(sc)*ew stored; is = 1/sum(exp) per node ----------------
__global__ __launch_bounds__(256) void score_kernel()
{
    int w    = (blockIdx.x * blockDim.x + threadIdx.x) >> 5;
    int lane = threadIdx.x & 31;
    if (w >= N_NODES) return;
    int node = w;
    int beg = g_rowptr[node], end = g_rowptr[node + 1];
    float4 erA = *reinterpret_cast<const float4*>(&g_er2[node * 8]);
    float4 erP = *reinterpret_cast<const float4*>(&g_er2[node * 8 + 4]);

    float s[8];
#pragma unroll
    for (int h = 0; h < 8; h++) s[h] = 0.f;

    for (int i = beg + lane; i < end; i += 32) {
        int sn = g_src_csr[i];
        float4 elA = *reinterpret_cast<const float4*>(&g_el2[sn * 8]);
        float4 elP = *reinterpret_cast<const float4*>(&g_el2[sn * 8 + 4]);
        float2 ew  = g_ew_csr[i];
        float e[8];
        e[0] = __expf(fminf(lrelu(elA.x + erA.x), 60.f));
        e[1] = __expf(fminf(lrelu(elA.y + erA.y), 60.f));
        e[2] = __expf(fminf(lrelu(elA.z + erA.z), 60.f));
        e[3] = __expf(fminf(lrelu(elA.w + erA.w), 60.f));
        e[4] = __expf(fminf(lrelu(elP.x + erP.x), 60.f));
        e[5] = __expf(fminf(lrelu(elP.y + erP.y), 60.f));
        e[6] = __expf(fminf(lrelu(elP.z + erP.z), 60.f));
        e[7] = __expf(fminf(lrelu(elP.w + erP.w), 60.f));
#pragma unroll
        for (int h = 0; h < 8; h++) s[h] += e[h];
        *reinterpret_cast<float4*>(&g_p[i * 8])     =
            make_float4(e[0] * ew.x, e[1] * ew.x, e[2] * ew.x, e[3] * ew.x);
        *reinterpret_cast<float4*>(&g_p[i * 8 + 4]) =
            make_float4(e[4] * ew.y, e[5] * ew.y, e[6] * ew.y, e[7] * ew.y);
    }
#pragma unroll
    for (int off = 16; off; off >>= 1)
#pragma unroll
        for (int h = 0; h < 8; h++)
            s[h] += __shfl_xor_sync(0xffffffffu, s[h], off);

    if (lane == 0) {
        *reinterpret_cast<float4*>(&g_is2[node * 8]) =
            make_float4(1.f / fmaxf(s[0], 1e-9f), 1.f / fmaxf(s[1], 1e-9f),
                        1.f / fmaxf(s[2], 1e-9f), 1.f / fmaxf(s[3], 1e-9f));
        *reinterpret_cast<float4*>(&g_is2[node * 8 + 4]) =
            make_float4(1.f / fmaxf(s[4], 1e-9f), 1.f / fmaxf(s[5], 1e-9f),
                        1.f / fmaxf(s[6], 1e-9f), 1.f / fmaxf(s[7], 1e-9f));
    }
}

// ---------------- aggregation: warp per node, both streams, 4-edge pipelined ----------------
// mode 0: outX[node][128] = relu(acc*is + biasX); mode 1: outX[node][32] = mean_h(acc*is + biasX)
__global__ __launch_bounds__(256) void agg_kernel(
    const float* __restrict__ ftA, const float* __restrict__ ftP,
    const float* __restrict__ biasA, const float* __restrict__ biasP,
    float* __restrict__ outA, float* __restrict__ outP, int mode)
{
    __shared__ float sh_pa[8][128];
    __shared__ float sh_pp[8][128];
    int wib  = threadIdx.x >> 5;
    int w    = (blockIdx.x * blockDim.x + threadIdx.x) >> 5;
    int lane = threadIdx.x & 31;
    if (w >= N_NODES) return;
    int node = w;
    int beg = g_rowptr[node], end = g_rowptr[node + 1];
    int h  = lane >> 3;
    int f0 = (lane & 7) * 4;
    float* pwA = sh_pa[wib];
    float* pwP = sh_pp[wib];

    float isA = g_is2[node * 8 + h];
    float isP = g_is2[node * 8 + 4 + h];

    float4 accA = make_float4(0.f, 0.f, 0.f, 0.f);
    float4 accP = make_float4(0.f, 0.f, 0.f, 0.f);

    for (int i0 = beg; i0 < end; i0 += 32) {
        int n = end - i0; if (n > 32) n = 32;
        int    sn_l = (lane < n) ? g_src_csr[i0 + lane] : 0;
        float4 pa   = (lane < n) ? *reinterpret_cast<const float4*>(&g_p[(i0 + lane) * 8])
                                 : make_float4(0.f, 0.f, 0.f, 0.f);
        float4 pp   = (lane < n) ? *reinterpret_cast<const float4*>(&g_p[(i0 + lane) * 8 + 4])
                                 : make_float4(0.f, 0.f, 0.f, 0.f);
        __syncwarp();
        *reinterpret_cast<float4*>(&pwA[lane * 4]) = pa;
        *reinterpret_cast<float4*>(&pwP[lane * 4]) = pp;
        __syncwarp();

        int j = 0;
        for (; j + 4 <= n; j += 4) {
            int s0 = __shfl_sync(0xffffffffu, sn_l, j);
            int s1 = __shfl_sync(0xffffffffu, sn_l, j + 1);
            int s2 = __shfl_sync(0xffffffffu, sn_l, j + 2);
            int s3 = __shfl_sync(0xffffffffu, sn_l, j + 3);
            float4 va0 = *reinterpret_cast<const float4*>(&ftA[s0 * DIM + lane * 4]);
            float4 vp0 = *reinterpret_cast<const float4*>(&ftP[s0 * DIM + lane * 4]);
            float4 va1 = *reinterpret_cast<const float4*>(&ftA[s1 * DIM + lane * 4]);
            float4 vp1 = *reinterpret_cast<const float4*>(&ftP[s1 * DIM + lane * 4]);
            float4 va2 = *reinterpret_cast<const float4*>(&ftA[s2 * DIM + lane * 4]);
            float4 vp2 = *reinterpret_cast<const float4*>(&ftP[s2 * DIM + lane * 4]);
            float4 va3 = *reinterpret_cast<const float4*>(&ftA[s3 * DIM + lane * 4]);
            float4 vp3 = *reinterpret_cast<const float4*>(&ftP[s3 * DIM + lane * 4]);
            float pA0 = pwA[(j    ) * 4 + h], pP0 = pwP[(j    ) * 4 + h];
            float pA1 = pwA[(j + 1) * 4 + h], pP1 = pwP[(j + 1) * 4 + h];
            float pA2 = pwA[(j + 2) * 4 + h], pP2 = pwP[(j + 2) * 4 + h];
            float pA3 = pwA[(j + 3) * 4 + h], pP3 = pwP[(j + 3) * 4 + h];
            accA.x = fmaf(pA0, va0.x, accA.x); accA.y = fmaf(pA0, va0.y, accA.y);
            accA.z = fmaf(pA0, va0.z, accA.z); accA.w = fmaf(pA0, va0.w, accA.w);
            accP.x = fmaf(pP0, vp0.x, accP.x); accP.y = fmaf(pP0, vp0.y, accP.y);
            accP.z = fmaf(pP0, vp0.z, accP.z); accP.w = fmaf(pP0, vp0.w, accP.w);
            accA.x = fmaf(pA1, va1.x, accA.x); accA.y = fmaf(pA1, va1.y, accA.y);
            accA.z = fmaf(pA1, va1.z, accA.z); accA.w = fmaf(pA1, va1.w, accA.w);
            accP.x = fmaf(pP1, vp1.x, accP.x); accP.y = fmaf(pP1, vp1.y, accP.y);
            accP.z = fmaf(pP1, vp1.z, accP.z); accP.w = fmaf(pP1, vp1.w, accP.w);
            accA.x = fmaf(pA2, va2.x, accA.x); accA.y = fmaf(pA2, va2.y, accA.y);
            accA.z = fmaf(pA2, va2.z, accA.z); accA.w = fmaf(pA2, va2.w, accA.w);
            accP.x = fmaf(pP2, vp2.x, accP.x); accP.y = fmaf(pP2, vp2.y, accP.y);
            accP.z = fmaf(pP2, vp2.z, accP.z); accP.w = fmaf(pP2, vp2.w, accP.w);
            accA.x = fmaf(pA3, va3.x, accA.x); accA.y = fmaf(pA3, va3.y, accA.y);
            accA.z = fmaf(pA3, va3.z, accA.z); accA.w = fmaf(pA3, va3.w, accA.w);
            accP.x = fmaf(pP3, vp3.x, accP.x); accP.y = fmaf(pP3, vp3.y, accP.y);
            accP.z = fmaf(pP3, vp3.z, accP.z); accP.w = fmaf(pP3, vp3.w, accP.w);
        }
        for (; j < n; j++) {
            int s0 = __shfl_sync(0xffffffffu, sn_l, j);
            float4 va0 = *reinterpret_cast<const float4*>(&ftA[s0 * DIM + lane * 4]);
            float4 vp0 = *reinterpret_cast<const float4*>(&ftP[s0 * DIM + lane * 4]);
            float pA0 = pwA[j * 4 + h], pP0 = pwP[j * 4 + h];
            accA.x = fmaf(pA0, va0.x, accA.x); accA.y = fmaf(pA0, va0.y, accA.y);
            accA.z = fmaf(pA0, va0.z, accA.z); accA.w = fmaf(pA0, va0.w, accA.w);
            accP.x = fmaf(pP0, vp0.x, accP.x); accP.y = fmaf(pP0, vp0.y, accP.y);
            accP.z = fmaf(pP0, vp0.z, accP.z); accP.w = fmaf(pP0, vp0.w, accP.w);
        }
    }

    float4 bA = *reinterpret_cast<const float4*>(&biasA[h * F + f0]);
    float4 bP = *reinterpret_cast<const float4*>(&biasP[h * F + f0]);
    accA.x = fmaf(accA.x, isA, bA.x); accA.y = fmaf(accA.y, isA, bA.y);
    accA.z = fmaf(accA.z, isA, bA.z); accA.w = fmaf(accA.w, isA, bA.w);
    accP.x = fmaf(accP.x, isP, bP.x); accP.y = fmaf(accP.y, isP, bP.y);
    accP.z = fmaf(accP.z, isP, bP.z); accP.w = fmaf(accP.w, isP, bP.w);

    if (mode == 0) {
        accA.x = fmaxf(accA.x, 0.f); accA.y = fmaxf(accA.y, 0.f);
        accA.z = fmaxf(accA.z, 0.f); accA.w = fmaxf(accA.w, 0.f);
        accP.x = fmaxf(accP.x, 0.f); accP.y = fmaxf(accP.y, 0.f);
        accP.z = fmaxf(accP.z, 0.f); accP.w = fmaxf(accP.w, 0.f);
        *reinterpret_cast<float4*>(&outA[node * DIM + lane * 4]) = accA;
        *reinterpret_cast<float4*>(&outP[node * DIM + lane * 4]) = accP;
    } else {
#pragma unroll
        for (int off = 8; off <= 16; off <<= 1) {
            accA.x += __shfl_xor_sync(0xffffffffu, accA.x, off);
            accA.y += __shfl_xor_sync(0xffffffffu, accA.y, off);
            accA.z += __shfl_xor_sync(0xffffffffu, accA.z, off);
            accA.w += __shfl_xor_sync(0xffffffffu, accA.w, off);
            accP.x += __shfl_xor_sync(0xffffffffu, accP.x, off);
            accP.y += __shfl_xor_sync(0xffffffffu, accP.y, off);
            accP.z += __shfl_xor_sync(0xffffffffu, accP.z, off);
            accP.w += __shfl_xor_sync(0xffffffffu, accP.w, off);
        }
        if (lane < 8) {
            *reinterpret_cast<float4*>(&outA[node * F + f0]) =
                make_float4(0.25f * accA.x, 0.25f * accA.y, 0.25f * accA.z, 0.25f * accA.w);
            *reinterpret_cast<float4*>(&outP[node * F + f0]) =
                make_float4(0.25f * accP.x, 0.25f * accP.y, 0.25f * accP.z, 0.25f * accP.w);
        }
    }
}

// ---------------- host orchestration ----------------
extern "C" void kernel_launch(void* const* d_in, const int* in_sizes, int n_in,
                              void* d_out, int out_size)
{
    const float* x_am     = (const float*)d_in[0];
    const float* x_ph     = (const float*)d_in[1];
    const float* exist    = (const float*)d_in[2];
    const float* am_exist = (const float*)d_in[3];

    const int *src, *dst;
    int wbase;
    if (in_sizes[4] == N_EDGES) { src = (const int*)d_in[4];  dst = (const int*)d_in[5];  wbase = 6; }
    else                        { src = (const int*)d_in[20]; dst = (const int*)d_in[21]; wbase = 4; }

    const float *Wg[4], *alg[4], *arg[4], *bg[4];
    for (int g = 0; g < 4; g++) {
        Wg[g]  = (const float*)d_in[wbase + g * 4 + 0];
        alg[g] = (const float*)d_in[wbase + g * 4 + 1];
        arg[g] = (const float*)d_in[wbase + g * 4 + 2];
        bg[g]  = (const float*)d_in[wbase + g * 4 + 3];
    }

    float* out = (float*)d_out;

    const int ZB = (N_NODES + 255) / 256;
    const int EB = (N_EDGES + 255) / 256;
    const int GB = (N_NODES + 63) / 64;
    const int NB = (N_NODES * 32 + 255) / 256;

    zero_cnt_kernel<<<ZB, 256>>>();
    hist_kernel<<<EB, 256>>>(dst);
    scan_kernel<<<1, 1024>>>();
    scatter_kernel<<<EB, 256>>>(src, dst, am_exist, exist);

    float *ftA, *ftP, *hA, *hP;
    cudaGetSymbolAddress((void**)&ftA, g_ft_a);
    cudaGetSymbolAddress((void**)&ftP, g_ft_p);
    cudaGetSymbolAddress((void**)&hA,  g_h_a);
    cudaGetSymbolAddress((void**)&hP,  g_h_p);

    dim3 gg(GB, 2);

    // layer 0 (am = stream 0, ph = stream 1)
    gemm_kernel<<<gg, 256>>>(x_am, x_ph, Wg[0], Wg[1], alg[0], alg[1], arg[0], arg[1], ftA, ftP);
    score_kernel<<<NB, 256>>>();
    agg_kernel<<<NB, 256>>>(ftA, ftP, bg[0], bg[1], hA, hP, 0);

    // layer 1 (+ fused head-mean)
    gemm_kernel<<<gg, 256>>>(hA, hP, Wg[2], Wg[3], alg[2], alg[3], arg[2], arg[3], ftA, ftP);
    score_kernel<<<NB, 256>>>();
    agg_kernel<<<NB, 256>>>(ftA, ftP, bg[2], bg[3], out, out + (size_t)N_NODES * F, 1);
}

// round 6
// speedup vs baseline: 2.1114x; 1.0268x over previous
#include <cuda_runtime.h>
#include <math.h>

#define N_NODES 50000
#define N_EDGES 800000
#define HEADS   4
#define F       32
#define DIM     128

typedef unsigned long long ull;

// ---------------- device scratch ----------------
__device__ float g_ft_a[N_NODES * DIM];
__device__ float g_ft_p[N_NODES * DIM];
__device__ float g_h_a [N_NODES * DIM];
__device__ float g_h_p [N_NODES * DIM];
__device__ float g_el2 [N_NODES * 8];       // [node][streamA 4 heads | streamP 4 heads]
__device__ float g_er2 [N_NODES * 8];
__device__ int   g_rowptr[N_NODES + 1];
__device__ int   g_cnt [N_NODES];
__device__ int   g_src_csr[N_EDGES];
__device__ float2 g_ew_csr[N_EDGES];        // {am_exist, exist}

// ---------------- f32x2 helpers ----------------
__device__ __forceinline__ ull dup2(float v) {
    ull r; asm("mov.b64 %0, {%1, %1};" : "=l"(r) : "f"(v)); return r;
}
__device__ __forceinline__ ull pk2(float a, float b) {
    ull r; asm("mov.b64 %0, {%1, %2};" : "=l"(r) : "f"(a), "f"(b)); return r;
}
__device__ __forceinline__ void ffma2(ull& d, ull a, ull b) {
    asm("fma.rn.f32x2 %0, %1, %2, %3;" : "=l"(d) : "l"(a), "l"(b), "l"(d));
}
__device__ __forceinline__ void unpk2(ull v, float& lo, float& hi) {
    asm("mov.b64 {%0, %1}, %2;" : "=f"(lo), "=f"(hi) : "l"(v));
}

// ---------------- CSR build ----------------
__global__ void zero_cnt_kernel() {
    int i = blockIdx.x * blockDim.x + threadIdx.x;
    if (i < N_NODES) g_cnt[i] = 0;
}

__global__ void hist_kernel(const int* __restrict__ dst) {
    int i = blockIdx.x * blockDim.x + threadIdx.x;
    if (i < N_EDGES) atomicAdd(&g_cnt[dst[i]], 1);
}

// scan + reset cnt for the scatter pass
__global__ void scan_kernel() {
    __shared__ int tmp[1024];
    int tid = threadIdx.x;
    const int chunk = (N_NODES + 1023) / 1024;
    int begin = tid * chunk;
    int end   = begin + chunk; if (end > N_NODES) end = N_NODES;
    int sum = 0;
    for (int i = begin; i < end && begin < N_NODES; i++) sum += g_cnt[i];
    tmp[tid] = sum;
    __syncthreads();
    for (int off = 1; off < 1024; off <<= 1) {
        int v = (tid >= off) ? tmp[tid - off] : 0;
        __syncthreads();
        tmp[tid] += v;
        __syncthreads();
    }
    int run = tmp[tid] - sum;
    for (int i = begin; i < end && begin < N_NODES; i++) {
        g_rowptr[i] = run;
        run += g_cnt[i];
        g_cnt[i] = 0;
    }
    if (tid == 1023) g_rowptr[N_NODES] = tmp[1023];
}

__global__ void scatter_kernel(const int* __restrict__ src, const int* __restrict__ dst,
                               const float* __restrict__ ewa, const float* __restrict__ ewp) {
    int i = blockIdx.x * blockDim.x + threadIdx.x;
    if (i < N_EDGES) {
        int d = dst[i];
        int pos = g_rowptr[d] + atomicAdd(&g_cnt[d], 1);
        g_src_csr[pos] = src[i];
        g_ew_csr[pos]  = make_float2(ewa[i], ewp[i]);
    }
}

// ---------------- GEMM (f32x2) + fused el/er; grid.y selects stream ----------------
__global__ __launch_bounds__(256) void gemm_kernel(
    const float* __restrict__ A0, const float* __restrict__ A1,
    const float* __restrict__ W0, const float* __restrict__ W1,
    const float* __restrict__ al0, const float* __restrict__ al1,
    const float* __restrict__ ar0, const float* __restrict__ ar1,
    float* __restrict__ C0, float* __restrict__ C1)
{
    int st = blockIdx.y;
    const float* A  = st ? A1  : A0;
    const float* W  = st ? W1  : W0;
    const float* al = st ? al1 : al0;
    const float* ar = st ? ar1 : ar0;
    float* C  = st ? C1  : C0;

    __shared__ __align__(16) float Ws[32 * 128];
    __shared__ __align__(16) float Xs[32 * 128];

    int tid = threadIdx.x;
    int m0  = blockIdx.x * 64;
    int tx  = tid & 31;
    int ty  = tid >> 5;

    ull acc[8][2];
#pragma unroll
    for (int i = 0; i < 8; i++) { acc[i][0] = 0ull; acc[i][1] = 0ull; }

    ull* Xp = (ull*)Xs;

    for (int kb = 0; kb < 128; kb += 32) {
        for (int i = tid * 4; i < 32 * 128; i += 1024)
            *reinterpret_cast<float4*>(&Ws[i]) =
                *reinterpret_cast<const float4*>(&W[(kb + (i >> 7)) * 128 + (i & 127)]);
        for (int i = tid; i < 64 * 8; i += 256) {
            int r = i & 63, kk4 = i >> 6;
            int m = m0 + r;
            float4 x4 = (m < N_NODES)
                ? *reinterpret_cast<const float4*>(&A[m * 128 + kb + kk4 * 4])
                : make_float4(0.f, 0.f, 0.f, 0.f);
            Xp[(kk4 * 4 + 0) * 64 + r] = dup2(x4.x);
            Xp[(kk4 * 4 + 1) * 64 + r] = dup2(x4.y);
            Xp[(kk4 * 4 + 2) * 64 + r] = dup2(x4.z);
            Xp[(kk4 * 4 + 3) * 64 + r] = dup2(x4.w);
        }
        __syncthreads();
#pragma unroll 8
        for (int kk = 0; kk < 32; kk++) {
            float4 b4 = *reinterpret_cast<const float4*>(&Ws[kk * 128 + tx * 4]);
            ull b01 = pk2(b4.x, b4.y);
            ull b23 = pk2(b4.z, b4.w);
            const ulonglong2* xr = reinterpret_cast<const ulonglong2*>(&Xp[kk * 64 + ty * 8]);
            ulonglong2 x01 = xr[0], x23 = xr[1], x45 = xr[2], x67 = xr[3];
            ffma2(acc[0][0], x01.x, b01); ffma2(acc[0][1], x01.x, b23);
            ffma2(acc[1][0], x01.y, b01); ffma2(acc[1][1], x01.y, b23);
            ffma2(acc[2][0], x23.x, b01); ffma2(acc[2][1], x23.x, b23);
            ffma2(acc[3][0], x23.y, b01); ffma2(acc[3][1], x23.y, b23);
            ffma2(acc[4][0], x45.x, b01); ffma2(acc[4][1], x45.x, b23);
            ffma2(acc[5][0], x45.y, b01); ffma2(acc[5][1], x45.y, b23);
            ffma2(acc[6][0], x67.x, b01); ffma2(acc[6][1], x67.x, b23);
            ffma2(acc[7][0], x67.y, b01); ffma2(acc[7][1], x67.y, b23);
        }
        __syncthreads();
    }

    float4 al4 = *reinterpret_cast<const float4*>(&al[tx * 4]);
    float4 ar4 = *reinterpret_cast<const float4*>(&ar[tx * 4]);
    int head = tx >> 3;

#pragma unroll
    for (int p = 0; p < 8; p++) {
        float4 o;
        unpk2(acc[p][0], o.x, o.y);
        unpk2(acc[p][1], o.z, o.w);
        int m = m0 + ty * 8 + p;
        if (m < N_NODES)
            *reinterpret_cast<float4*>(&C[m * 128 + tx * 4]) = o;
        float l = o.x * al4.x + o.y * al4.y + o.z * al4.z + o.w * al4.w;
        float r = o.x * ar4.x + o.y * ar4.y + o.z * ar4.z + o.w * ar4.w;
#pragma unroll
        for (int off = 1; off <= 4; off <<= 1) {
            l += __shfl_xor_sync(0xffffffffu, l, off);
            r += __shfl_xor_sync(0xffffffffu, r, off);
        }
        if ((tx & 7) == 0 && m < N_NODES) {
            g_el2[m * 8 + st * 4 + head] = l;
            g_er2[m * 8 + st * 4 + head] = r;
        }
    }
}

__device__ __forceinline__ float lrelu(float x) { return x > 0.f ? x : 0.2f * x; }

// ---------------- fused score + aggregation: warp per node, both streams ----------------
// out = (Σ_e exp(sc)·ew·v) / Σ_e exp(sc) + bias  (relu for mode 0, head-mean for mode 1)
__global__ __launch_bounds__(256) void agg_kernel(
    const float* __restrict__ ftA, const float* __restrict__ ftP,
    const float* __restrict__ biasA, const float* __restrict__ biasP,
    float* __restrict__ outA, float* __restrict__ outP, int mode)
{
    __shared__ float sh_pa[8][128];
    __shared__ float sh_pp[8][128];
    int wib  = threadIdx.x >> 5;
    int w    = (blockIdx.x * blockDim.x + threadIdx.x) >> 5;
    int lane = threadIdx.x & 31;
    if (w >= N_NODES) return;
    int node = w;
    int beg = g_rowptr[node], end = g_rowptr[node + 1];
    int h  = lane >> 3;
    int f0 = (lane & 7) * 4;
    float* pwA = sh_pa[wib];
    float* pwP = sh_pp[wib];

    float4 erA = *reinterpret_cast<const float4*>(&g_er2[node * 8]);
    float4 erP = *reinterpret_cast<const float4*>(&g_er2[node * 8 + 4]);

    float s[8];
#pragma unroll
    for (int q = 0; q < 8; q++) s[q] = 0.f;

    float4 accA = make_float4(0.f, 0.f, 0.f, 0.f);
    float4 accP = make_float4(0.f, 0.f, 0.f, 0.f);

    for (int i0 = beg; i0 < end; i0 += 32) {
        int n = end - i0; if (n > 32) n = 32;
        int sn_l = 0;
        float4 pa = make_float4(0.f, 0.f, 0.f, 0.f);
        float4 pp = make_float4(0.f, 0.f, 0.f, 0.f);
        if (lane < n) {
            int i = i0 + lane;
            sn_l = g_src_csr[i];
            float2 ew  = g_ew_csr[i];
            float4 elA = *reinterpret_cast<const float4*>(&g_el2[sn_l * 8]);
            float4 elP = *reinterpret_cast<const float4*>(&g_el2[sn_l * 8 + 4]);
            float e0 = __expf(fminf(lrelu(elA.x + erA.x), 60.f));
            float e1 = __expf(fminf(lrelu(elA.y + erA.y), 60.f));
            float e2 = __expf(fminf(lrelu(elA.z + erA.z), 60.f));
            float e3 = __expf(fminf(lrelu(elA.w + erA.w), 60.f));
            float e4 = __expf(fminf(lrelu(elP.x + erP.x), 60.f));
            float e5 = __expf(fminf(lrelu(elP.y + erP.y), 60.f));
            float e6 = __expf(fminf(lrelu(elP.z + erP.z), 60.f));
            float e7 = __expf(fminf(lrelu(elP.w + erP.w), 60.f));
            s[0] += e0; s[1] += e1; s[2] += e2; s[3] += e3;
            s[4] += e4; s[5] += e5; s[6] += e6; s[7] += e7;
            pa = make_float4(e0 * ew.x, e1 * ew.x, e2 * ew.x, e3 * ew.x);
            pp = make_float4(e4 * ew.y, e5 * ew.y, e6 * ew.y, e7 * ew.y);
        }
        __syncwarp();
        *reinterpret_cast<float4*>(&pwA[lane * 4]) = pa;
        *reinterpret_cast<float4*>(&pwP[lane * 4]) = pp;
        __syncwarp();

        int j = 0;
        for (; j + 4 <= n; j += 4) {
            int s0 = __shfl_sync(0xffffffffu, sn_l, j);
            int s1 = __shfl_sync(0xffffffffu, sn_l, j + 1);
            int s2 = __shfl_sync(0xffffffffu, sn_l, j + 2);
            int s3 = __shfl_sync(0xffffffffu, sn_l, j + 3);
            float4 va0 = *reinterpret_cast<const float4*>(&ftA[s0 * DIM + lane * 4]);
            float4 vp0 = *reinterpret_cast<const float4*>(&ftP[s0 * DIM + lane * 4]);
            float4 va1 = *reinterpret_cast<const float4*>(&ftA[s1 * DIM + lane * 4]);
            float4 vp1 = *reinterpret_cast<const float4*>(&ftP[s1 * DIM + lane * 4]);
            float4 va2 = *reinterpret_cast<const float4*>(&ftA[s2 * DIM + lane * 4]);
            float4 vp2 = *reinterpret_cast<const float4*>(&ftP[s2 * DIM + lane * 4]);
            float4 va3 = *reinterpret_cast<const float4*>(&ftA[s3 * DIM + lane * 4]);
            float4 vp3 = *reinterpret_cast<const float4*>(&ftP[s3 * DIM + lane * 4]);
            float pA0 = pwA[(j    ) * 4 + h], pP0 = pwP[(j    ) * 4 + h];
            float pA1 = pwA[(j + 1) * 4 + h], pP1 = pwP[(j + 1) * 4 + h];
            float pA2 = pwA[(j + 2) * 4 + h], pP2 = pwP[(j + 2) * 4 + h];
            float pA3 = pwA[(j + 3) * 4 + h], pP3 = pwP[(j + 3) * 4 + h];
            accA.x = fmaf(pA0, va0.x, accA.x); accA.y = fmaf(pA0, va0.y, accA.y);
            accA.z = fmaf(pA0, va0.z, accA.z); accA.w = fmaf(pA0, va0.w, accA.w);
            accP.x = fmaf(pP0, vp0.x, accP.x); accP.y = fmaf(pP0, vp0.y, accP.y);
            accP.z = fmaf(pP0, vp0.z, accP.z); accP.w = fmaf(pP0, vp0.w, accP.w);
            accA.x = fmaf(pA1, va1.x, accA.x); accA.y = fmaf(pA1, va1.y, accA.y);
            accA.z = fmaf(pA1, va1.z, accA.z); accA.w = fmaf(pA1, va1.w, accA.w);
            accP.x = fmaf(pP1, vp1.x, accP.x); accP.y = fmaf(pP1, vp1.y, accP.y);
            accP.z = fmaf(pP1, vp1.z, accP.z); accP.w = fmaf(pP1, vp1.w, accP.w);
            accA.x = fmaf(pA2, va2.x, accA.x); accA.y = fmaf(pA2, va2.y, accA.y);
            accA.z = fmaf(pA2, va2.z, accA.z); accA.w = fmaf(pA2, va2.w, accA.w);
            accP.x = fmaf(pP2, vp2.x, accP.x); accP.y = fmaf(pP2, vp2.y, accP.y);
            accP.z = fmaf(pP2, vp2.z, accP.z); accP.w = fmaf(pP2, vp2.w, accP.w);
            accA.x = fmaf(pA3, va3.x, accA.x); accA.y = fmaf(pA3, va3.y, accA.y);
            accA.z = fmaf(pA3, va3.z, accA.z); accA.w = fmaf(pA3, va3.w, accA.w);
            accP.x = fmaf(pP3, vp3.x, accP.x); accP.y = fmaf(pP3, vp3.y, accP.y);
            accP.z = fmaf(pP3, vp3.z, accP.z); accP.w = fmaf(pP3, vp3.w, accP.w);
        }
        for (; j < n; j++) {
            int s0 = __shfl_sync(0xffffffffu, sn_l, j);
            float4 va0 = *reinterpret_cast<const float4*>(&ftA[s0 * DIM + lane * 4]);
            float4 vp0 = *reinterpret_cast<const float4*>(&ftP[s0 * DIM + lane * 4]);
            float pA0 = pwA[j * 4 + h], pP0 = pwP[j * 4 + h];
            accA.x = fmaf(pA0, va0.x, accA.x); accA.y = fmaf(pA0, va0.y, accA.y);
            accA.z = fmaf(pA0, va0.z, accA.z); accA.w = fmaf(pA0, va0.w, accA.w);
            accP.x = fmaf(pP0, vp0.x, accP.x); accP.y = fmaf(pP0, vp0.y, accP.y);
            accP.z = fmaf(pP0, vp0.z, accP.z); accP.w = fmaf(pP0, vp0.w, accP.w);
        }
    }

    // warp-reduce exp sums (all lanes end up with full sums)
#pragma unroll
    for (int off = 16; off; off >>= 1)
#pragma unroll
        for (int q = 0; q < 8; q++)
            s[q] += __shfl_xor_sync(0xffffffffu, s[q], off);

    float isA = 1.f / fmaxf(s[h],     1e-9f);
    float isP = 1.f / fmaxf(s[4 + h], 1e-9f);

    float4 bA = *reinterpret_cast<const float4*>(&biasA[h * F + f0]);
    float4 bP = *reinterpret_cast<const float4*>(&biasP[h * F + f0]);
    accA.x = fmaf(accA.x, isA, bA.x); accA.y = fmaf(accA.y, isA, bA.y);
    accA.z = fmaf(accA.z, isA, bA.z); accA.w = fmaf(accA.w, isA, bA.w);
    accP.x = fmaf(accP.x, isP, bP.x); accP.y = fmaf(accP.y, isP, bP.y);
    accP.z = fmaf(accP.z, isP, bP.z); accP.w = fmaf(accP.w, isP, bP.w);

    if (mode == 0) {
        accA.x = fmaxf(accA.x, 0.f); accA.y = fmaxf(accA.y, 0.f);
        accA.z = fmaxf(accA.z, 0.f); accA.w = fmaxf(accA.w, 0.f);
        accP.x = fmaxf(accP.x, 0.f); accP.y = fmaxf(accP.y, 0.f);
        accP.z = fmaxf(accP.z, 0.f); accP.w = fmaxf(accP.w, 0.f);
        *reinterpret_cast<float4*>(&outA[node * DIM + lane * 4]) = accA;
        *reinterpret_cast<float4*>(&outP[node * DIM + lane * 4]) = accP;
    } else {
#pragma unroll
        for (int off = 8; off <= 16; off <<= 1) {
            accA.x += __shfl_xor_sync(0xffffffffu, accA.x, off);
            accA.y += __shfl_xor_sync(0xffffffffu, accA.y, off);
            accA.z += __shfl_xor_sync(0xffffffffu, accA.z, off);
            accA.w += __shfl_xor_sync(0xffffffffu, accA.w, off);
            accP.x += __shfl_xor_sync(0xffffffffu, accP.x, off);
            accP.y += __shfl_xor_sync(0xffffffffu, accP.y, off);
            accP.z += __shfl_xor_sync(0xffffffffu, accP.z, off);
            accP.w += __shfl_xor_sync(0xffffffffu, accP.w, off);
        }
        if (lane < 8) {
            *reinterpret_cast<float4*>(&outA[node * F + f0]) =
                make_float4(0.25f * accA.x, 0.25f * accA.y, 0.25f * accA.z, 0.25f * accA.w);
            *reinterpret_cast<float4*>(&outP[node * F + f0]) =
                make_float4(0.25f * accP.x, 0.25f * accP.y, 0.25f * accP.z, 0.25f * accP.w);
        }
    }
}

// ---------------- host orchestration ----------------
extern "C" void kernel_launch(void* const* d_in, const int* in_sizes, int n_in,
                              void* d_out, int out_size)
{
    const float* x_am     = (const float*)d_in[0];
    const float* x_ph     = (const float*)d_in[1];
    const float* exist    = (const float*)d_in[2];
    const float* am_exist = (const float*)d_in[3];

    const int *src, *dst;
    int wbase;
    if (in_sizes[4] == N_EDGES) { src = (const int*)d_in[4];  dst = (const int*)d_in[5];  wbase = 6; }
    else                        { src = (const int*)d_in[20]; dst = (const int*)d_in[21]; wbase = 4; }

    const float *Wg[4], *alg[4], *arg[4], *bg[4];
    for (int g = 0; g < 4; g++) {
        Wg[g]  = (const float*)d_in[wbase + g * 4 + 0];
        alg[g] = (const float*)d_in[wbase + g * 4 + 1];
        arg[g] = (const float*)d_in[wbase + g * 4 + 2];
        bg[g]  = (const float*)d_in[wbase + g * 4 + 3];
    }

    float* out = (float*)d_out;

    const int ZB = (N_NODES + 255) / 256;
    const int EB = (N_EDGES + 255) / 256;
    const int GB = (N_NODES + 63) / 64;
    const int NB = (N_NODES * 32 + 255) / 256;

    zero_cnt_kernel<<<ZB, 256>>>();
    hist_kernel<<<EB, 256>>>(dst);
    scan_kernel<<<1, 1024>>>();
    scatter_kernel<<<EB, 256>>>(src, dst, am_exist, exist);

    float *ftA, *ftP, *hA, *hP;
    cudaGetSymbolAddress((void**)&ftA, g_ft_a);
    cudaGetSymbolAddress((void**)&ftP, g_ft_p);
    cudaGetSymbolAddress((void**)&hA,  g_h_a);
    cudaGetSymbolAddress((void**)&hP,  g_h_p);

    dim3 gg(GB, 2);

    // layer 0 (am = stream 0, ph = stream 1)
    gemm_kernel<<<gg, 256>>>(x_am, x_ph, Wg[0], Wg[1], alg[0], alg[1], arg[0], arg[1], ftA, ftP);
    agg_kernel<<<NB, 256>>>(ftA, ftP, bg[0], bg[1], hA, hP, 0);

    // layer 1 (+ fused head-mean)
    gemm_kernel<<<gg, 256>>>(hA, hP, Wg[2], Wg[3], alg[2], alg[3], arg[2], arg[3], ftA, ftP);
    agg_kernel<<<NB, 256>>>(ftA, ftP, bg[2], bg[3], out, out + (size_t)N_NODES * F, 1);
}

// round 7
// speedup vs baseline: 2.3036x; 1.0910x over previous
#include <cuda_runtime.h>
#include <cuda_fp16.h>
#include <math.h>

#define N_NODES 50000
#define N_EDGES 800000
#define HEADS   4
#define F       32
#define DIM     128

typedef unsigned long long ull;

// ---------------- device scratch ----------------
__device__ __half g_ft16_a[N_NODES * DIM];   // ft in fp16 (only consumer: agg gathers)
__device__ __half g_ft16_p[N_NODES * DIM];
__device__ float  g_h_a [N_NODES * DIM];     // layer-0 output (fp32, GEMM input)
__device__ float  g_h_p [N_NODES * DIM];
__device__ float  g_el2 [N_NODES * 8];       // [node][streamA 4 heads | streamP 4 heads]
__device__ float  g_er2 [N_NODES * 8];
__device__ int    g_rowptr[N_NODES + 1];
__device__ int    g_cnt [N_NODES];
__device__ int    g_src_csr[N_EDGES];
__device__ float2 g_ew_csr[N_EDGES];         // {am_exist, exist}

// ---------------- f32x2 helpers ----------------
__device__ __forceinline__ ull dup2(float v) {
    ull r; asm("mov.b64 %0, {%1, %1};" : "=l"(r) : "f"(v)); return r;
}
__device__ __forceinline__ ull pk2(float a, float b) {
    ull r; asm("mov.b64 %0, {%1, %2};" : "=l"(r) : "f"(a), "f"(b)); return r;
}
__device__ __forceinline__ void ffma2(ull& d, ull a, ull b) {
    asm("fma.rn.f32x2 %0, %1, %2, %3;" : "=l"(d) : "l"(a), "l"(b), "l"(d));
}
__device__ __forceinline__ void unpk2(ull v, float& lo, float& hi) {
    asm("mov.b64 {%0, %1}, %2;" : "=f"(lo), "=f"(hi) : "l"(v));
}

// ---------------- CSR build ----------------
__global__ void zero_cnt_kernel() {
    int i = blockIdx.x * blockDim.x + threadIdx.x;
    if (i < N_NODES) g_cnt[i] = 0;
}

__global__ void hist_kernel(const int* __restrict__ dst) {
    int i = blockIdx.x * blockDim.x + threadIdx.x;
    if (i < N_EDGES) atomicAdd(&g_cnt[dst[i]], 1);
}

__global__ void scan_kernel() {
    __shared__ int tmp[1024];
    int tid = threadIdx.x;
    const int chunk = (N_NODES + 1023) / 1024;
    int begin = tid * chunk;
    int end   = begin + chunk; if (end > N_NODES) end = N_NODES;
    int sum = 0;
    for (int i = begin; i < end && begin < N_NODES; i++) sum += g_cnt[i];
    tmp[tid] = sum;
    __syncthreads();
    for (int off = 1; off < 1024; off <<= 1) {
        int v = (tid >= off) ? tmp[tid - off] : 0;
        __syncthreads();
        tmp[tid] += v;
        __syncthreads();
    }
    int run = tmp[tid] - sum;
    for (int i = begin; i < end && begin < N_NODES; i++) {
        g_rowptr[i] = run;
        run += g_cnt[i];
        g_cnt[i] = 0;
    }
    if (tid == 1023) g_rowptr[N_NODES] = tmp[1023];
}

__global__ void scatter_kernel(const int* __restrict__ src, const int* __restrict__ dst,
                               const float* __restrict__ ewa, const float* __restrict__ ewp) {
    int i = blockIdx.x * blockDim.x + threadIdx.x;
    if (i < N_EDGES) {
        int d = dst[i];
        int pos = g_rowptr[d] + atomicAdd(&g_cnt[d], 1);
        g_src_csr[pos] = src[i];
        g_ew_csr[pos]  = make_float2(ewa[i], ewp[i]);
    }
}

// ---------------- GEMM (f32x2) + fused el/er; fp16 ft output ----------------
__global__ __launch_bounds__(256) void gemm_kernel(
    const float* __restrict__ A0, const float* __restrict__ A1,
    const float* __restrict__ W0, const float* __restrict__ W1,
    const float* __restrict__ al0, const float* __restrict__ al1,
    const float* __restrict__ ar0, const float* __restrict__ ar1,
    __half* __restrict__ C0, __half* __restrict__ C1)
{
    int st = blockIdx.y;
    const float* A  = st ? A1  : A0;
    const float* W  = st ? W1  : W0;
    const float* al = st ? al1 : al0;
    const float* ar = st ? ar1 : ar0;
    __half* C = st ? C1 : C0;

    __shared__ __align__(16) float Ws[32 * 128];
    __shared__ __align__(16) float Xs[32 * 128];

    int tid = threadIdx.x;
    int m0  = blockIdx.x * 64;
    int tx  = tid & 31;
    int ty  = tid >> 5;

    ull acc[8][2];
#pragma unroll
    for (int i = 0; i < 8; i++) { acc[i][0] = 0ull; acc[i][1] = 0ull; }

    ull* Xp = (ull*)Xs;

    for (int kb = 0; kb < 128; kb += 32) {
        for (int i = tid * 4; i < 32 * 128; i += 1024)
            *reinterpret_cast<float4*>(&Ws[i]) =
                *reinterpret_cast<const float4*>(&W[(kb + (i >> 7)) * 128 + (i & 127)]);
        for (int i = tid; i < 64 * 8; i += 256) {
            int r = i & 63, kk4 = i >> 6;
            int m = m0 + r;
            float4 x4 = (m < N_NODES)
                ? *reinterpret_cast<const float4*>(&A[m * 128 + kb + kk4 * 4])
                : make_float4(0.f, 0.f, 0.f, 0.f);
            Xp[(kk4 * 4 + 0) * 64 + r] = dup2(x4.x);
            Xp[(kk4 * 4 + 1) * 64 + r] = dup2(x4.y);
            Xp[(kk4 * 4 + 2) * 64 + r] = dup2(x4.z);
            Xp[(kk4 * 4 + 3) * 64 + r] = dup2(x4.w);
        }
        __syncthreads();
#pragma unroll 8
        for (int kk = 0; kk < 32; kk++) {
            float4 b4 = *reinterpret_cast<const float4*>(&Ws[kk * 128 + tx * 4]);
            ull b01 = pk2(b4.x, b4.y);
            ull b23 = pk2(b4.z, b4.w);
            const ulonglong2* xr = reinterpret_cast<const ulonglong2*>(&Xp[kk * 64 + ty * 8]);
            ulonglong2 x01 = xr[0], x23 = xr[1], x45 = xr[2], x67 = xr[3];
            ffma2(acc[0][0], x01.x, b01); ffma2(acc[0][1], x01.x, b23);
            ffma2(acc[1][0], x01.y, b01); ffma2(acc[1][1], x01.y, b23);
            ffma2(acc[2][0], x23.x, b01); ffma2(acc[2][1], x23.x, b23);
            ffma2(acc[3][0], x23.y, b01); ffma2(acc[3][1], x23.y, b23);
            ffma2(acc[4][0], x45.x, b01); ffma2(acc[4][1], x45.x, b23);
            ffma2(acc[5][0], x45.y, b01); ffma2(acc[5][1], x45.y, b23);
            ffma2(acc[6][0], x67.x, b01); ffma2(acc[6][1], x67.x, b23);
            ffma2(acc[7][0], x67.y, b01); ffma2(acc[7][1], x67.y, b23);
        }
        __syncthreads();
    }

    float4 al4 = *reinterpret_cast<const float4*>(&al[tx * 4]);
    float4 ar4 = *reinterpret_cast<const float4*>(&ar[tx * 4]);
    int head = tx >> 3;

#pragma unroll
    for (int p = 0; p < 8; p++) {
        float4 o;
        unpk2(acc[p][0], o.x, o.y);
        unpk2(acc[p][1], o.z, o.w);
        int m = m0 + ty * 8 + p;
        if (m < N_NODES) {
            __half2 h0 = __floats2half2_rn(o.x, o.y);
            __half2 h1 = __floats2half2_rn(o.z, o.w);
            uint2 u;
            u.x = *reinterpret_cast<unsigned*>(&h0);
            u.y = *reinterpret_cast<unsigned*>(&h1);
            *reinterpret_cast<uint2*>(&C[m * DIM + tx * 4]) = u;
        }
        float l = o.x * al4.x + o.y * al4.y + o.z * al4.z + o.w * al4.w;
        float r = o.x * ar4.x + o.y * ar4.y + o.z * ar4.z + o.w * ar4.w;
#pragma unroll
        for (int off = 1; off <= 4; off <<= 1) {
            l += __shfl_xor_sync(0xffffffffu, l, off);
            r += __shfl_xor_sync(0xffffffffu, r, off);
        }
        if ((tx & 7) == 0 && m < N_NODES) {
            g_el2[m * 8 + st * 4 + head] = l;
            g_er2[m * 8 + st * 4 + head] = r;
        }
    }
}

__device__ __forceinline__ float lrelu(float x) { return x > 0.f ? x : 0.2f * x; }

__device__ __forceinline__ float4 ld_half4(const __half* p) {
    uint2 u = *reinterpret_cast<const uint2*>(p);
    float2 f0 = __half22float2(*reinterpret_cast<__half2*>(&u.x));
    float2 f1 = __half22float2(*reinterpret_cast<__half2*>(&u.y));
    return make_float4(f0.x, f0.y, f1.x, f1.y);
}

// ---------------- fused score + aggregation: warp per node, both streams ----------------
__global__ __launch_bounds__(256) void agg_kernel(
    const __half* __restrict__ ftA, const __half* __restrict__ ftP,
    const float* __restrict__ biasA, const float* __restrict__ biasP,
    float* __restrict__ outA, float* __restrict__ outP, int mode)
{
    __shared__ float sh_pa[8][128];
    __shared__ float sh_pp[8][128];
    int wib  = threadIdx.x >> 5;
    int w    = (blockIdx.x * blockDim.x + threadIdx.x) >> 5;
    int lane = threadIdx.x & 31;
    if (w >= N_NODES) return;
    int node = w;
    int beg = g_rowptr[node], end = g_rowptr[node + 1];
    int h  = lane >> 3;
    int f0 = (lane & 7) * 4;
    float* pwA = sh_pa[wib];
    float* pwP = sh_pp[wib];

    float4 erA = *reinterpret_cast<const float4*>(&g_er2[node * 8]);
    float4 erP = *reinterpret_cast<const float4*>(&g_er2[node * 8 + 4]);

    float s[8];
#pragma unroll
    for (int q = 0; q < 8; q++) s[q] = 0.f;

    float4 accA = make_float4(0.f, 0.f, 0.f, 0.f);
    float4 accP = make_float4(0.f, 0.f, 0.f, 0.f);

    for (int i0 = beg; i0 < end; i0 += 32) {
        int n = end - i0; if (n > 32) n = 32;
        int sn_l = 0;
        float4 pa = make_float4(0.f, 0.f, 0.f, 0.f);
        float4 pp = make_float4(0.f, 0.f, 0.f, 0.f);
        if (lane < n) {
            int i = i0 + lane;
            sn_l = g_src_csr[i];
            float2 ew  = g_ew_csr[i];
            float4 elA = *reinterpret_cast<const float4*>(&g_el2[sn_l * 8]);
            float4 elP = *reinterpret_cast<const float4*>(&g_el2[sn_l * 8 + 4]);
            float e0 = __expf(fminf(lrelu(elA.x + erA.x), 60.f));
            float e1 = __expf(fminf(lrelu(elA.y + erA.y), 60.f));
            float e2 = __expf(fminf(lrelu(elA.z + erA.z), 60.f));
            float e3 = __expf(fminf(lrelu(elA.w + erA.w), 60.f));
            float e4 = __expf(fminf(lrelu(elP.x + erP.x), 60.f));
            float e5 = __expf(fminf(lrelu(elP.y + erP.y), 60.f));
            float e6 = __expf(fminf(lrelu(elP.z + erP.z), 60.f));
            float e7 = __expf(fminf(lrelu(elP.w + erP.w), 60.f));
            s[0] += e0; s[1] += e1; s[2] += e2; s[3] += e3;
            s[4] += e4; s[5] += e5; s[6] += e6; s[7] += e7;
            pa = make_float4(e0 * ew.x, e1 * ew.x, e2 * ew.x, e3 * ew.x);
            pp = make_float4(e4 * ew.y, e5 * ew.y, e6 * ew.y, e7 * ew.y);
        }
        __syncwarp();
        *reinterpret_cast<float4*>(&pwA[lane * 4]) = pa;
        *reinterpret_cast<float4*>(&pwP[lane * 4]) = pp;
        __syncwarp();

        int j = 0;
        for (; j + 4 <= n; j += 4) {
            int s0 = __shfl_sync(0xffffffffu, sn_l, j);
            int s1 = __shfl_sync(0xffffffffu, sn_l, j + 1);
            int s2 = __shfl_sync(0xffffffffu, sn_l, j + 2);
            int s3 = __shfl_sync(0xffffffffu, sn_l, j + 3);
            float4 va0 = ld_half4(&ftA[s0 * DIM + lane * 4]);
            float4 vp0 = ld_half4(&ftP[s0 * DIM + lane * 4]);
            float4 va1 = ld_half4(&ftA[s1 * DIM + lane * 4]);
            float4 vp1 = ld_half4(&ftP[s1 * DIM + lane * 4]);
            float4 va2 = ld_half4(&ftA[s2 * DIM + lane * 4]);
            float4 vp2 = ld_half4(&ftP[s2 * DIM + lane * 4]);
            float4 va3 = ld_half4(&ftA[s3 * DIM + lane * 4]);
            float4 vp3 = ld_half4(&ftP[s3 * DIM + lane * 4]);
            float pA0 = pwA[(j    ) * 4 + h], pP0 = pwP[(j    ) * 4 + h];
            float pA1 = pwA[(j + 1) * 4 + h], pP1 = pwP[(j + 1) * 4 + h];
            float pA2 = pwA[(j + 2) * 4 + h], pP2 = pwP[(j + 2) * 4 + h];
            float pA3 = pwA[(j + 3) * 4 + h], pP3 = pwP[(j + 3) * 4 + h];
            accA.x = fmaf(pA0, va0.x, accA.x); accA.y = fmaf(pA0, va0.y, accA.y);
            accA.z = fmaf(pA0, va0.z, accA.z); accA.w = fmaf(pA0, va0.w, accA.w);
            accP.x = fmaf(pP0, vp0.x, accP.x); accP.y = fmaf(pP0, vp0.y, accP.y);
            accP.z = fmaf(pP0, vp0.z, accP.z); accP.w = fmaf(pP0, vp0.w, accP.w);
            accA.x = fmaf(pA1, va1.x, accA.x); accA.y = fmaf(pA1, va1.y, accA.y);
            accA.z = fmaf(pA1, va1.z, accA.z); accA.w = fmaf(pA1, va1.w, accA.w);
            accP.x = fmaf(pP1, vp1.x, accP.x); accP.y = fmaf(pP1, vp1.y, accP.y);
            accP.z = fmaf(pP1, vp1.z, accP.z); accP.w = fmaf(pP1, vp1.w, accP.w);
            accA.x = fmaf(pA2, va2.x, accA.x); accA.y = fmaf(pA2, va2.y, accA.y);
            accA.z = fmaf(pA2, va2.z, accA.z); accA.w = fmaf(pA2, va2.w, accA.w);
            accP.x = fmaf(pP2, vp2.x, accP.x); accP.y = fmaf(pP2, vp2.y, accP.y);
            accP.z = fmaf(pP2, vp2.z, accP.z); accP.w = fmaf(pP2, vp2.w, accP.w);
            accA.x = fmaf(pA3, va3.x, accA.x); accA.y = fmaf(pA3, va3.y, accA.y);
            accA.z = fmaf(pA3, va3.z, accA.z); accA.w = fmaf(pA3, va3.w, accA.w);
            accP.x = fmaf(pP3, vp3.x, accP.x); accP.y = fmaf(pP3, vp3.y, accP.y);
            accP.z = fmaf(pP3, vp3.z, accP.z); accP.w = fmaf(pP3, vp3.w, accP.w);
        }
        for (; j < n; j++) {
            int s0 = __shfl_sync(0xffffffffu, sn_l, j);
            float4 va0 = ld_half4(&ftA[s0 * DIM + lane * 4]);
            float4 vp0 = ld_half4(&ftP[s0 * DIM + lane * 4]);
            float pA0 = pwA[j * 4 + h], pP0 = pwP[j * 4 + h];
            accA.x = fmaf(pA0, va0.x, accA.x); accA.y = fmaf(pA0, va0.y, accA.y);
            accA.z = fmaf(pA0, va0.z, accA.z); accA.w = fmaf(pA0, va0.w, accA.w);
            accP.x = fmaf(pP0, vp0.x, accP.x); accP.y = fmaf(pP0, vp0.y, accP.y);
            accP.z = fmaf(pP0, vp0.z, accP.z); accP.w = fmaf(pP0, vp0.w, accP.w);
        }
    }

#pragma unroll
    for (int off = 16; off; off >>= 1)
#pragma unroll
        for (int q = 0; q < 8; q++)
            s[q] += __shfl_xor_sync(0xffffffffu, s[q], off);

    float isA = 1.f / fmaxf(s[h],     1e-9f);
    float isP = 1.f / fmaxf(s[4 + h], 1e-9f);

    float4 bA = *reinterpret_cast<const float4*>(&biasA[h * F + f0]);
    float4 bP = *reinterpret_cast<const float4*>(&biasP[h * F + f0]);
    accA.x = fmaf(accA.x, isA, bA.x); accA.y = fmaf(accA.y, isA, bA.y);
    accA.z = fmaf(accA.z, isA, bA.z); accA.w = fmaf(accA.w, isA, bA.w);
    accP.x = fmaf(accP.x, isP, bP.x); accP.y = fmaf(accP.y, isP, bP.y);
    accP.z = fmaf(accP.z, isP, bP.z); accP.w = fmaf(accP.w, isP, bP.w);

    if (mode == 0) {
        accA.x = fmaxf(accA.x, 0.f); accA.y = fmaxf(accA.y, 0.f);
        accA.z = fmaxf(accA.z, 0.f); accA.w = fmaxf(accA.w, 0.f);
        accP.x = fmaxf(accP.x, 0.f); accP.y = fmaxf(accP.y, 0.f);
        accP.z = fmaxf(accP.z, 0.f); accP.w = fmaxf(accP.w, 0.f);
        *reinterpret_cast<float4*>(&outA[node * DIM + lane * 4]) = accA;
        *reinterpret_cast<float4*>(&outP[node * DIM + lane * 4]) = accP;
    } else {
#pragma unroll
        for (int off = 8; off <= 16; off <<= 1) {
            accA.x += __shfl_xor_sync(0xffffffffu, accA.x, off);
            accA.y += __shfl_xor_sync(0xffffffffu, accA.y, off);
            accA.z += __shfl_xor_sync(0xffffffffu, accA.z, off);
            accA.w += __shfl_xor_sync(0xffffffffu, accA.w, off);
            accP.x += __shfl_xor_sync(0xffffffffu, accP.x, off);
            accP.y += __shfl_xor_sync(0xffffffffu, accP.y, off);
            accP.z += __shfl_xor_sync(0xffffffffu, accP.z, off);
            accP.w += __shfl_xor_sync(0xffffffffu, accP.w, off);
        }
        if (lane < 8) {
            *reinterpret_cast<float4*>(&outA[node * F + f0]) =
                make_float4(0.25f * accA.x, 0.25f * accA.y, 0.25f * accA.z, 0.25f * accA.w);
            *reinterpret_cast<float4*>(&outP[node * F + f0]) =
                make_float4(0.25f * accP.x, 0.25f * accP.y, 0.25f * accP.z, 0.25f * accP.w);
        }
    }
}

// ---------------- host orchestration ----------------
extern "C" void kernel_launch(void* const* d_in, const int* in_sizes, int n_in,
                              void* d_out, int out_size)
{
    const float* x_am     = (const float*)d_in[0];
    const float* x_ph     = (const float*)d_in[1];
    const float* exist    = (const float*)d_in[2];
    const float* am_exist = (const float*)d_in[3];

    const int *src, *dst;
    int wbase;
    if (in_sizes[4] == N_EDGES) { src = (const int*)d_in[4];  dst = (const int*)d_in[5];  wbase = 6; }
    else                        { src = (const int*)d_in[20]; dst = (const int*)d_in[21]; wbase = 4; }

    const float *Wg[4], *alg[4], *arg[4], *bg[4];
    for (int g = 0; g < 4; g++) {
        Wg[g]  = (const float*)d_in[wbase + g * 4 + 0];
        alg[g] = (const float*)d_in[wbase + g * 4 + 1];
        arg[g] = (const float*)d_in[wbase + g * 4 + 2];
        bg[g]  = (const float*)d_in[wbase + g * 4 + 3];
    }

    float* out = (float*)d_out;

    const int ZB = (N_NODES + 255) / 256;
    const int EB = (N_EDGES + 255) / 256;
    const int GB = (N_NODES + 63) / 64;
    const int NB = (N_NODES * 32 + 255) / 256;

    zero_cnt_kernel<<<ZB, 256>>>();
    hist_kernel<<<EB, 256>>>(dst);
    scan_kernel<<<1, 1024>>>();
    scatter_kernel<<<EB, 256>>>(src, dst, am_exist, exist);

    __half *ftA, *ftP;
    float *hA, *hP;
    cudaGetSymbolAddress((void**)&ftA, g_ft16_a);
    cudaGetSymbolAddress((void**)&ftP, g_ft16_p);
    cudaGetSymbolAddress((void**)&hA,  g_h_a);
    cudaGetSymbolAddress((void**)&hP,  g_h_p);

    dim3 gg(GB, 2);

    // layer 0 (am = stream 0, ph = stream 1)
    gemm_kernel<<<gg, 256>>>(x_am, x_ph, Wg[0], Wg[1], alg[0], alg[1], arg[0], arg[1], ftA, ftP);
    agg_kernel<<<NB, 256>>>(ftA, ftP, bg[0], bg[1], hA, hP, 0);

    // layer 1 (+ fused head-mean)
    gemm_kernel<<<gg, 256>>>(hA, hP, Wg[2], Wg[3], alg[2], alg[3], arg[2], arg[3], ftA, ftP);
    agg_kernel<<<NB, 256>>>(ftA, ftP, bg[2], bg[3], out, out + (size_t)N_NODES * F, 1);
}

// round 8
// speedup vs baseline: 2.5246x; 1.0959x over previous
#include <cuda_runtime.h>
#include <cuda_fp16.h>
#include <math.h>

#define N_NODES 50000
#define N_EDGES 800000
#define HEADS   4
#define F       32
#define DIM     128
#define DIM2    256   // interleaved row: [A 128 | P 128]

typedef unsigned long long ull;

// ---------------- device scratch ----------------
__device__ __half g_ft16[N_NODES * DIM2];    // interleaved fp16 ft, both streams
__device__ float  g_h_a [N_NODES * DIM];     // layer-0 output (fp32, GEMM input)
__device__ float  g_h_p [N_NODES * DIM];
__device__ float  g_el2 [N_NODES * 8];       // [node][A 4 heads | P 4 heads]
__device__ float  g_er2 [N_NODES * 8];
__device__ int    g_rowptr[N_NODES + 1];
__device__ int    g_cnt [N_NODES];
__device__ int    g_src_csr[N_EDGES];
__device__ float2 g_ew_csr[N_EDGES];         // {am_exist, exist}

// ---------------- f32x2 helpers ----------------
__device__ __forceinline__ ull dup2(float v) {
    ull r; asm("mov.b64 %0, {%1, %1};" : "=l"(r) : "f"(v)); return r;
}
__device__ __forceinline__ ull pk2(float a, float b) {
    ull r; asm("mov.b64 %0, {%1, %2};" : "=l"(r) : "f"(a), "f"(b)); return r;
}
__device__ __forceinline__ void ffma2(ull& d, ull a, ull b) {
    asm("fma.rn.f32x2 %0, %1, %2, %3;" : "=l"(d) : "l"(a), "l"(b), "l"(d));
}
__device__ __forceinline__ void unpk2(ull v, float& lo, float& hi) {
    asm("mov.b64 {%0, %1}, %2;" : "=f"(lo), "=f"(hi) : "l"(v));
}

// ---------------- CSR build ----------------
__global__ void zero_cnt_kernel() {
    int i = blockIdx.x * blockDim.x + threadIdx.x;
    if (i < N_NODES) g_cnt[i] = 0;
}

__global__ void hist_kernel(const int* __restrict__ dst) {
    int i = blockIdx.x * blockDim.x + threadIdx.x;
    if (i < N_EDGES) atomicAdd(&g_cnt[dst[i]], 1);
}

__global__ void scan_kernel() {
    __shared__ int tmp[1024];
    int tid = threadIdx.x;
    const int chunk = (N_NODES + 1023) / 1024;
    int begin = tid * chunk;
    int end   = begin + chunk; if (end > N_NODES) end = N_NODES;
    int sum = 0;
    for (int i = begin; i < end && begin < N_NODES; i++) sum += g_cnt[i];
    tmp[tid] = sum;
    __syncthreads();
    for (int off = 1; off < 1024; off <<= 1) {
        int v = (tid >= off) ? tmp[tid - off] : 0;
        __syncthreads();
        tmp[tid] += v;
        __syncthreads();
    }
    int run = tmp[tid] - sum;
    for (int i = begin; i < end && begin < N_NODES; i++) {
        g_rowptr[i] = run;
        run += g_cnt[i];
        g_cnt[i] = 0;
    }
    if (tid == 1023) g_rowptr[N_NODES] = tmp[1023];
}

__global__ void scatter_kernel(const int* __restrict__ src, const int* __restrict__ dst,
                               const float* __restrict__ ewa, const float* __restrict__ ewp) {
    int i = blockIdx.x * blockDim.x + threadIdx.x;
    if (i < N_EDGES) {
        int d = dst[i];
        int pos = g_rowptr[d] + atomicAdd(&g_cnt[d], 1);
        g_src_csr[pos] = src[i];
        g_ew_csr[pos]  = make_float2(ewa[i], ewp[i]);
    }
}

// ---------------- GEMM (f32x2) + fused el/er; fp16 interleaved ft output ----------------
__global__ __launch_bounds__(256) void gemm_kernel(
    const float* __restrict__ A0, const float* __restrict__ A1,
    const float* __restrict__ W0, const float* __restrict__ W1,
    const float* __restrict__ al0, const float* __restrict__ al1,
    const float* __restrict__ ar0, const float* __restrict__ ar1,
    __half* __restrict__ C)
{
    int st = blockIdx.y;
    const float* A  = st ? A1  : A0;
    const float* W  = st ? W1  : W0;
    const float* al = st ? al1 : al0;
    const float* ar = st ? ar1 : ar0;

    __shared__ __align__(16) float Ws[32 * 128];
    __shared__ __align__(16) float Xs[32 * 128];

    int tid = threadIdx.x;
    int m0  = blockIdx.x * 64;
    int tx  = tid & 31;
    int ty  = tid >> 5;

    ull acc[8][2];
#pragma unroll
    for (int i = 0; i < 8; i++) { acc[i][0] = 0ull; acc[i][1] = 0ull; }

    ull* Xp = (ull*)Xs;

    for (int kb = 0; kb < 128; kb += 32) {
        for (int i = tid * 4; i < 32 * 128; i += 1024)
            *reinterpret_cast<float4*>(&Ws[i]) =
                *reinterpret_cast<const float4*>(&W[(kb + (i >> 7)) * 128 + (i & 127)]);
        for (int i = tid; i < 64 * 8; i += 256) {
            int r = i & 63, kk4 = i >> 6;
            int m = m0 + r;
            float4 x4 = (m < N_NODES)
                ? *reinterpret_cast<const float4*>(&A[m * 128 + kb + kk4 * 4])
                : make_float4(0.f, 0.f, 0.f, 0.f);
            Xp[(kk4 * 4 + 0) * 64 + r] = dup2(x4.x);
            Xp[(kk4 * 4 + 1) * 64 + r] = dup2(x4.y);
            Xp[(kk4 * 4 + 2) * 64 + r] = dup2(x4.z);
            Xp[(kk4 * 4 + 3) * 64 + r] = dup2(x4.w);
        }
        __syncthreads();
#pragma unroll 8
        for (int kk = 0; kk < 32; kk++) {
            float4 b4 = *reinterpret_cast<const float4*>(&Ws[kk * 128 + tx * 4]);
            ull b01 = pk2(b4.x, b4.y);
            ull b23 = pk2(b4.z, b4.w);
            const ulonglong2* xr = reinterpret_cast<const ulonglong2*>(&Xp[kk * 64 + ty * 8]);
            ulonglong2 x01 = xr[0], x23 = xr[1], x45 = xr[2], x67 = xr[3];
            ffma2(acc[0][0], x01.x, b01); ffma2(acc[0][1], x01.x, b23);
            ffma2(acc[1][0], x01.y, b01); ffma2(acc[1][1], x01.y, b23);
            ffma2(acc[2][0], x23.x, b01); ffma2(acc[2][1], x23.x, b23);
            ffma2(acc[3][0], x23.y, b01); ffma2(acc[3][1], x23.y, b23);
            ffma2(acc[4][0], x45.x, b01); ffma2(acc[4][1], x45.x, b23);
            ffma2(acc[5][0], x45.y, b01); ffma2(acc[5][1], x45.y, b23);
            ffma2(acc[6][0], x67.x, b01); ffma2(acc[6][1], x67.x, b23);
            ffma2(acc[7][0], x67.y, b01); ffma2(acc[7][1], x67.y, b23);
        }
        __syncthreads();
    }

    float4 al4 = *reinterpret_cast<const float4*>(&al[tx * 4]);
    float4 ar4 = *reinterpret_cast<const float4*>(&ar[tx * 4]);
    int head = tx >> 3;

#pragma unroll
    for (int p = 0; p < 8; p++) {
        float4 o;
        unpk2(acc[p][0], o.x, o.y);
        unpk2(acc[p][1], o.z, o.w);
        int m = m0 + ty * 8 + p;
        if (m < N_NODES) {
            __half2 h0 = __floats2half2_rn(o.x, o.y);
            __half2 h1 = __floats2half2_rn(o.z, o.w);
            uint2 u;
            u.x = *reinterpret_cast<unsigned*>(&h0);
            u.y = *reinterpret_cast<unsigned*>(&h1);
            *reinterpret_cast<uint2*>(&C[m * DIM2 + st * DIM + tx * 4]) = u;
        }
        float l = o.x * al4.x + o.y * al4.y + o.z * al4.z + o.w * al4.w;
        float r = o.x * ar4.x + o.y * ar4.y + o.z * ar4.z + o.w * ar4.w;
#pragma unroll
        for (int off = 1; off <= 4; off <<= 1) {
            l += __shfl_xor_sync(0xffffffffu, l, off);
            r += __shfl_xor_sync(0xffffffffu, r, off);
        }
        if ((tx & 7) == 0 && m < N_NODES) {
            g_el2[m * 8 + st * 4 + head] = l;
            g_er2[m * 8 + st * 4 + head] = r;
        }
    }
}

__device__ __forceinline__ float lrelu(float x) { return x > 0.f ? x : 0.2f * x; }

__device__ __forceinline__ void acc8(float* acc, uint4 u, float p) {
    float2 f0 = __half22float2(*reinterpret_cast<__half2*>(&u.x));
    float2 f1 = __half22float2(*reinterpret_cast<__half2*>(&u.y));
    float2 f2 = __half22float2(*reinterpret_cast<__half2*>(&u.z));
    float2 f3 = __half22float2(*reinterpret_cast<__half2*>(&u.w));
    acc[0] = fmaf(p, f0.x, acc[0]); acc[1] = fmaf(p, f0.y, acc[1]);
    acc[2] = fmaf(p, f1.x, acc[2]); acc[3] = fmaf(p, f1.y, acc[3]);
    acc[4] = fmaf(p, f2.x, acc[4]); acc[5] = fmaf(p, f2.y, acc[5]);
    acc[6] = fmaf(p, f3.x, acc[6]); acc[7] = fmaf(p, f3.y, acc[7]);
}

// ---------------- fused score + aggregation: warp per node, half-warp per stream ----------------
// lanes 0-15: stream A, lanes 16-31: stream P; each lane owns 8 features.
__global__ __launch_bounds__(256) void agg_kernel(
    const __half* __restrict__ ft,
    const float* __restrict__ biasA, const float* __restrict__ biasP,
    float* __restrict__ outA, float* __restrict__ outP, int mode)
{
    __shared__ float sh_p[8][256];     // per warp: 32 edges x 8 p-values
    int wib  = threadIdx.x >> 5;
    int w    = (blockIdx.x * blockDim.x + threadIdx.x) >> 5;
    int lane = threadIdx.x & 31;
    if (w >= N_NODES) return;
    int node = w;
    int beg = g_rowptr[node], end = g_rowptr[node + 1];
    int part = lane >> 4;              // 0 = A, 1 = P
    int q    = lane & 15;              // feature-group within stream
    int h    = q >> 2;                 // head
    int r    = q & 3;                  // 8-feature subgroup within head
    int ph   = part * 4 + h;           // p index for this lane
    int off  = part * DIM + q * 8;     // byte-element offset within ft row
    float* pw = sh_p[wib];

    float4 erA = *reinterpret_cast<const float4*>(&g_er2[node * 8]);
    float4 erP = *reinterpret_cast<const float4*>(&g_er2[node * 8 + 4]);

    float s[8];
#pragma unroll
    for (int k = 0; k < 8; k++) s[k] = 0.f;
    float acc[8];
#pragma unroll
    for (int k = 0; k < 8; k++) acc[k] = 0.f;

    for (int i0 = beg; i0 < end; i0 += 32) {
        int n = end - i0; if (n > 32) n = 32;
        int sn_l = 0;
        float4 pa = make_float4(0.f, 0.f, 0.f, 0.f);
        float4 pp = make_float4(0.f, 0.f, 0.f, 0.f);
        if (lane < n) {
            int i = i0 + lane;
            sn_l = g_src_csr[i];
            float2 ew  = g_ew_csr[i];
            float4 elA = *reinterpret_cast<const float4*>(&g_el2[sn_l * 8]);
            float4 elP = *reinterpret_cast<const float4*>(&g_el2[sn_l * 8 + 4]);
            float e0 = __expf(fminf(lrelu(elA.x + erA.x), 60.f));
            float e1 = __expf(fminf(lrelu(elA.y + erA.y), 60.f));
            float e2 = __expf(fminf(lrelu(elA.z + erA.z), 60.f));
            float e3 = __expf(fminf(lrelu(elA.w + erA.w), 60.f));
            float e4 = __expf(fminf(lrelu(elP.x + erP.x), 60.f));
            float e5 = __expf(fminf(lrelu(elP.y + erP.y), 60.f));
            float e6 = __expf(fminf(lrelu(elP.z + erP.z), 60.f));
            float e7 = __expf(fminf(lrelu(elP.w + erP.w), 60.f));
            s[0] += e0; s[1] += e1; s[2] += e2; s[3] += e3;
            s[4] += e4; s[5] += e5; s[6] += e6; s[7] += e7;
            pa = make_float4(e0 * ew.x, e1 * ew.x, e2 * ew.x, e3 * ew.x);
            pp = make_float4(e4 * ew.y, e5 * ew.y, e6 * ew.y, e7 * ew.y);
        }
        __syncwarp();
        *reinterpret_cast<float4*>(&pw[lane * 8])     = pa;
        *reinterpret_cast<float4*>(&pw[lane * 8 + 4]) = pp;
        __syncwarp();

        int j = 0;
        for (; j + 4 <= n; j += 4) {
            int s0 = __shfl_sync(0xffffffffu, sn_l, j);
            int s1 = __shfl_sync(0xffffffffu, sn_l, j + 1);
            int s2 = __shfl_sync(0xffffffffu, sn_l, j + 2);
            int s3 = __shfl_sync(0xffffffffu, sn_l, j + 3);
            uint4 u0 = *reinterpret_cast<const uint4*>(&ft[(size_t)s0 * DIM2 + off]);
            uint4 u1 = *reinterpret_cast<const uint4*>(&ft[(size_t)s1 * DIM2 + off]);
            uint4 u2 = *reinterpret_cast<const uint4*>(&ft[(size_t)s2 * DIM2 + off]);
            uint4 u3 = *reinterpret_cast<const uint4*>(&ft[(size_t)s3 * DIM2 + off]);
            float p0 = pw[(j    ) * 8 + ph];
            float p1 = pw[(j + 1) * 8 + ph];
            float p2 = pw[(j + 2) * 8 + ph];
            float p3 = pw[(j + 3) * 8 + ph];
            acc8(acc, u0, p0);
            acc8(acc, u1, p1);
            acc8(acc, u2, p2);
            acc8(acc, u3, p3);
        }
        for (; j < n; j++) {
            int s0 = __shfl_sync(0xffffffffu, sn_l, j);
            uint4 u0 = *reinterpret_cast<const uint4*>(&ft[(size_t)s0 * DIM2 + off]);
            float p0 = pw[j * 8 + ph];
            acc8(acc, u0, p0);
        }
    }

    // warp-reduce exp sums
#pragma unroll
    for (int o = 16; o; o >>= 1)
#pragma unroll
        for (int k = 0; k < 8; k++)
            s[k] += __shfl_xor_sync(0xffffffffu, s[k], o);

    float is = 1.f / fmaxf(s[ph], 1e-9f);

    const float* bias = part ? biasP : biasA;
    float4 b0 = *reinterpret_cast<const float4*>(&bias[h * F + r * 8]);
    float4 b1 = *reinterpret_cast<const float4*>(&bias[h * F + r * 8 + 4]);
    acc[0] = fmaf(acc[0], is, b0.x); acc[1] = fmaf(acc[1], is, b0.y);
    acc[2] = fmaf(acc[2], is, b0.z); acc[3] = fmaf(acc[3], is, b0.w);
    acc[4] = fmaf(acc[4], is, b1.x); acc[5] = fmaf(acc[5], is, b1.y);
    acc[6] = fmaf(acc[6], is, b1.z); acc[7] = fmaf(acc[7], is, b1.w);

    float* out = part ? outP : outA;

    if (mode == 0) {
#pragma unroll
        for (int k = 0; k < 8; k++) acc[k] = fmaxf(acc[k], 0.f);
        *reinterpret_cast<float4*>(&out[node * DIM + q * 8]) =
            make_float4(acc[0], acc[1], acc[2], acc[3]);
        *reinterpret_cast<float4*>(&out[node * DIM + q * 8 + 4]) =
            make_float4(acc[4], acc[5], acc[6], acc[7]);
    } else {
        // mean over heads: combine lanes differing in h (offsets 4, 8 within 16-lane group)
#pragma unroll
        for (int o = 4; o <= 8; o <<= 1)
#pragma unroll
            for (int k = 0; k < 8; k++)
                acc[k] += __shfl_xor_sync(0xffffffffu, acc[k], o);
        if (h == 0) {
            *reinterpret_cast<float4*>(&out[node * F + r * 8]) =
                make_float4(0.25f * acc[0], 0.25f * acc[1], 0.25f * acc[2], 0.25f * acc[3]);
            *reinterpret_cast<float4*>(&out[node * F + r * 8 + 4]) =
                make_float4(0.25f * acc[4], 0.25f * acc[5], 0.25f * acc[6], 0.25f * acc[7]);
        }
    }
}

// ---------------- host orchestration ----------------
extern "C" void kernel_launch(void* const* d_in, const int* in_sizes, int n_in,
                              void* d_out, int out_size)
{
    const float* x_am     = (const float*)d_in[0];
    const float* x_ph     = (const float*)d_in[1];
    const float* exist    = (const float*)d_in[2];
    const float* am_exist = (const float*)d_in[3];

    const int *src, *dst;
    int wbase;
    if (in_sizes[4] == N_EDGES) { src = (const int*)d_in[4];  dst = (const int*)d_in[5];  wbase = 6; }
    else                        { src = (const int*)d_in[20]; dst = (const int*)d_in[21]; wbase = 4; }

    const float *Wg[4], *alg[4], *arg[4], *bg[4];
    for (int g = 0; g < 4; g++) {
        Wg[g]  = (const float*)d_in[wbase + g * 4 + 0];
        alg[g] = (const float*)d_in[wbase + g * 4 + 1];
        arg[g] = (const float*)d_in[wbase + g * 4 + 2];
        bg[g]  = (const float*)d_in[wbase + g * 4 + 3];
    }

    float* out = (float*)d_out;

    const int ZB = (N_NODES + 255) / 256;
    const int EB = (N_EDGES + 255) / 256;
    const int GB = (N_NODES + 63) / 64;
    const int NB = (N_NODES * 32 + 255) / 256;

    __half* ft;
    float *hA, *hP;
    cudaGetSymbolAddress((void**)&ft, g_ft16);
    cudaGetSymbolAddress((void**)&hA, g_h_a);
    cudaGetSymbolAddress((void**)&hP, g_h_p);

    // lazily create side stream + events (first call = uncaptured correctness run)
    static cudaStream_t side = nullptr;
    static cudaEvent_t evFork = nullptr, evCsr = nullptr;
    if (!side) {
        cudaStreamCreateWithFlags(&side, cudaStreamNonBlocking);
        cudaEventCreateWithFlags(&evFork, cudaEventDisableTiming);
        cudaEventCreateWithFlags(&evCsr,  cudaEventDisableTiming);
    }

    dim3 gg(GB, 2);

    // fork: CSR build on side stream, layer-0 GEMM on main stream
    cudaEventRecord(evFork, 0);
    cudaStreamWaitEvent(side, evFork, 0);
    zero_cnt_kernel<<<ZB, 256, 0, side>>>();
    hist_kernel<<<EB, 256, 0, side>>>(dst);
    scan_kernel<<<1, 1024, 0, side>>>();
    scatter_kernel<<<EB, 256, 0, side>>>(src, dst, am_exist, exist);
    cudaEventRecord(evCsr, side);

    gemm_kernel<<<gg, 256>>>(x_am, x_ph, Wg[0], Wg[1], alg[0], alg[1], arg[0], arg[1], ft);

    // join: agg0 needs both CSR and GEMM0
    cudaStreamWaitEvent(0, evCsr, 0);
    agg_kernel<<<NB, 256>>>(ft, bg[0], bg[1], hA, hP, 0);

    // layer 1 (+ fused head-mean)
    gemm_kernel<<<gg, 256>>>(hA, hP, Wg[2], Wg[3], alg[2], alg[3], arg[2], arg[3], ft);
    agg_kernel<<<NB, 256>>>(ft, bg[2], bg[3], out, out + (size_t)N_NODES * F, 1);
}